// round 1
// baseline (speedup 1.0000x reference)
#include <cuda_runtime.h>
#include <math.h>

#define BATCH 2
#define CCH 512
#define NH 8
#define HD 64
#define GROUPS 32
#define NTOK 4096
#define EPS 1e-5f

// ---------------- scratch (static device globals; no allocation) -------------
__device__ float g_hn[(size_t)BATCH * CCH * NTOK];          // 16 MB  groupnorm out
__device__ float g_qkv[(size_t)BATCH * 3 * CCH * NTOK];     // 50 MB  qkv
__device__ float g_attn[(size_t)BATCH * NH * NTOK * NTOK];  // 1  GB  attention scores
__device__ float g_ao[(size_t)BATCH * CCH * NTOK];          // 16 MB  attn output

// ---------------- GroupNorm ---------------------------------------------------
// one block per (batch, group); group = 16 channels x 4096 spatial = 65536 elems
__global__ void groupnorm_kernel(const float* __restrict__ x,
                                 const float* __restrict__ w,
                                 const float* __restrict__ b) {
    const int CPG = CCH / GROUPS;  // 16
    int bg = blockIdx.x;
    int bb = bg / GROUPS;
    int g  = bg % GROUPS;
    const float* xp = x + ((size_t)bb * CCH + (size_t)g * CPG) * NTOK;
    float*       hp = g_hn + ((size_t)bb * CCH + (size_t)g * CPG) * NTOK;
    int tid = threadIdx.x;
    const int TOT = CPG * NTOK;

    float s = 0.f, s2 = 0.f;
    for (int i = tid; i < TOT; i += blockDim.x) {
        float v = xp[i];
        s += v; s2 += v * v;
    }
    __shared__ float sh[256], sh2[256];
    sh[tid] = s; sh2[tid] = s2;
    __syncthreads();
    for (int o = 128; o > 0; o >>= 1) {
        if (tid < o) { sh[tid] += sh[tid + o]; sh2[tid] += sh2[tid + o]; }
        __syncthreads();
    }
    float mean = sh[0] / TOT;
    float var  = sh2[0] / TOT - mean * mean;
    float inv  = rsqrtf(var + EPS);

    for (int i = tid; i < TOT; i += blockDim.x) {
        int ch = g * CPG + i / NTOK;
        hp[i] = (xp[i] - mean) * inv * w[ch] + b[ch];
    }
}

// ---------------- generic tiled SGEMM -----------------------------------------
// C[m,n] = alpha * sum_k A[m,k] * B[k,n]  (+ bias[m]) (+ resid[m,n])
// TA: A stored K x M (A[m,k] = A[k*lda + m]), else M x K (A[m*lda + k])
// TB: B stored N x K (B[k,n] = B[n*ldb + k]), else K x N (B[k*ldb + n])
// blockIdx.z advances A/B/C/resid by sA/sB/sC/sR elements (batched).
// Tiles: 64x64 output, BK=16; 256 threads; 4x4 per thread.
template <bool TA, bool TB>
__global__ void sgemm_k(const float* __restrict__ A, const float* __restrict__ Bm,
                        float* __restrict__ Cm,
                        int M, int Np, int K, int lda, int ldb, int ldc,
                        size_t sA, size_t sB, size_t sC,
                        float alpha, const float* __restrict__ bias,
                        const float* __restrict__ resid, size_t sR) {
    A  += (size_t)blockIdx.z * sA;
    Bm += (size_t)blockIdx.z * sB;
    Cm += (size_t)blockIdx.z * sC;
    if (resid) resid += (size_t)blockIdx.z * sR;

    __shared__ float As[16][64];
    __shared__ float Bs[16][64];

    const int tid = threadIdx.x;        // 0..255
    const int tx = tid & 15;            // n dir
    const int ty = tid >> 4;            // m dir
    const int row0 = blockIdx.y * 64;
    const int col0 = blockIdx.x * 64;

    float acc[4][4];
#pragma unroll
    for (int i = 0; i < 4; i++)
#pragma unroll
        for (int j = 0; j < 4; j++) acc[i][j] = 0.f;

    for (int k0 = 0; k0 < K; k0 += 16) {
        // load A tile -> As[k][m]
        if (!TA) {
#pragma unroll
            for (int l = tid; l < 64 * 16; l += 256) {
                int m = l >> 4, k = l & 15;
                As[k][m] = A[(size_t)(row0 + m) * lda + (k0 + k)];
            }
        } else {
#pragma unroll
            for (int l = tid; l < 64 * 16; l += 256) {
                int k = l >> 6, m = l & 63;
                As[k][m] = A[(size_t)(k0 + k) * lda + (row0 + m)];
            }
        }
        // load B tile -> Bs[k][n]
        if (!TB) {
#pragma unroll
            for (int l = tid; l < 16 * 64; l += 256) {
                int k = l >> 6, n = l & 63;
                Bs[k][n] = Bm[(size_t)(k0 + k) * ldb + (col0 + n)];
            }
        } else {
#pragma unroll
            for (int l = tid; l < 64 * 16; l += 256) {
                int n = l >> 4, k = l & 15;
                Bs[k][n] = Bm[(size_t)(col0 + n) * ldb + (k0 + k)];
            }
        }
        __syncthreads();

#pragma unroll
        for (int k = 0; k < 16; k++) {
            float a[4], bv[4];
#pragma unroll
            for (int i = 0; i < 4; i++) a[i] = As[k][ty * 4 + i];
#pragma unroll
            for (int j = 0; j < 4; j++) bv[j] = Bs[k][tx * 4 + j];
#pragma unroll
            for (int i = 0; i < 4; i++)
#pragma unroll
                for (int j = 0; j < 4; j++)
                    acc[i][j] = fmaf(a[i], bv[j], acc[i][j]);
        }
        __syncthreads();
    }

#pragma unroll
    for (int i = 0; i < 4; i++) {
        int m = row0 + ty * 4 + i;
        float bi = bias ? bias[m] : 0.f;
#pragma unroll
        for (int j = 0; j < 4; j++) {
            int n = col0 + tx * 4 + j;
            float v = acc[i][j] * alpha + bi;
            if (resid) v += resid[(size_t)m * ldc + n];
            Cm[(size_t)m * ldc + n] = v;
        }
    }
}

// ---------------- softmax over last dim (4096), in place ----------------------
__global__ void softmax_kernel(float* __restrict__ attn) {
    float* p = attn + (size_t)blockIdx.x * NTOK;
    int tid = threadIdx.x;  // 256
    float vals[16];
    float mx = -INFINITY;
#pragma unroll
    for (int i = 0; i < 16; i++) {
        vals[i] = p[tid + i * 256];
        mx = fmaxf(mx, vals[i]);
    }
    __shared__ float sh[256];
    sh[tid] = mx;
    __syncthreads();
    for (int o = 128; o > 0; o >>= 1) {
        if (tid < o) sh[tid] = fmaxf(sh[tid], sh[tid + o]);
        __syncthreads();
    }
    mx = sh[0];
    __syncthreads();
    float s = 0.f;
#pragma unroll
    for (int i = 0; i < 16; i++) {
        vals[i] = __expf(vals[i] - mx);
        s += vals[i];
    }
    sh[tid] = s;
    __syncthreads();
    for (int o = 128; o > 0; o >>= 1) {
        if (tid < o) sh[tid] += sh[tid + o];
        __syncthreads();
    }
    float inv = 1.0f / sh[0];
#pragma unroll
    for (int i = 0; i < 16; i++) p[tid + i * 256] = vals[i] * inv;
}

// ---------------- launch ------------------------------------------------------
extern "C" void kernel_launch(void* const* d_in, const int* in_sizes, int n_in,
                              void* d_out, int out_size) {
    const float* x      = (const float*)d_in[0];
    const float* norm_w = (const float*)d_in[1];
    const float* norm_b = (const float*)d_in[2];
    const float* qkv_w  = (const float*)d_in[3];
    const float* qkv_b  = (const float*)d_in[4];
    const float* proj_w = (const float*)d_in[5];
    const float* proj_b = (const float*)d_in[6];
    float* out = (float*)d_out;

    float *hn, *qkv, *attn, *ao;
    cudaGetSymbolAddress((void**)&hn,   g_hn);
    cudaGetSymbolAddress((void**)&qkv,  g_qkv);
    cudaGetSymbolAddress((void**)&attn, g_attn);
    cudaGetSymbolAddress((void**)&ao,   g_ao);

    const size_t CN   = (size_t)CCH * NTOK;   // 512*4096
    const size_t HDN  = (size_t)HD * NTOK;    // 64*4096
    const size_t NN   = (size_t)NTOK * NTOK;  // 4096*4096

    // 1) GroupNorm
    groupnorm_kernel<<<BATCH * GROUPS, 256>>>(x, norm_w, norm_b);

    // 2) QKV GEMM: [1536,512] x [512,4096] per batch (z = batch)
    sgemm_k<false, false><<<dim3(NTOK / 64, (3 * CCH) / 64, BATCH), 256>>>(
        qkv_w, hn, qkv,
        3 * CCH, NTOK, CCH, CCH, NTOK, NTOK,
        (size_t)0, CN, 3 * CN,
        1.0f, qkv_b, nullptr, 0);

    // 3) scores: attn[n,m] = (1/8) * sum_d q[d,n] k[d,m]   (z = head)
    const float scale = 0.125f;  // 64^-0.5
    for (int b = 0; b < BATCH; b++) {
        const float* qb = qkv + (size_t)b * 3 * CN;            // q
        const float* kb = qkv + (size_t)b * 3 * CN + CN;       // k
        float* ab = attn + (size_t)b * NH * NN;
        sgemm_k<true, false><<<dim3(NTOK / 64, NTOK / 64, NH), 256>>>(
            qb, kb, ab,
            NTOK, NTOK, HD, NTOK, NTOK, NTOK,
            HDN, HDN, NN,
            scale, nullptr, nullptr, 0);
    }

    // 4) softmax rows
    softmax_kernel<<<BATCH * NH * NTOK, 256>>>(attn);

    // 5) AV: ao[d,n] = sum_m v[d,m] * attn[n,m]   (z = head)
    for (int b = 0; b < BATCH; b++) {
        const float* vb = qkv + (size_t)b * 3 * CN + 2 * CN;
        const float* ab = attn + (size_t)b * NH * NN;
        float* ob = ao + (size_t)b * CN;
        sgemm_k<false, true><<<dim3(NTOK / 64, HD / 64, NH), 256>>>(
            vb, ab, ob,
            HD, NTOK, NTOK, NTOK, NTOK, NTOK,
            HDN, NN, HDN,
            1.0f, nullptr, nullptr, 0);
    }

    // 6) proj + bias + residual: out = proj_w @ ao + proj_b + x   (z = batch)
    sgemm_k<false, false><<<dim3(NTOK / 64, CCH / 64, BATCH), 256>>>(
        proj_w, ao, out,
        CCH, NTOK, CCH, CCH, NTOK, NTOK,
        (size_t)0, CN, CN,
        1.0f, proj_b, x, CN);
}

// round 2
// speedup vs baseline: 1.7262x; 1.7262x over previous
#include <cuda_runtime.h>
#include <math.h>

#define BATCH 2
#define CCH 512
#define NH 8
#define HD 64
#define GROUPS 32
#define NTOK 4096
#define EPS 1e-5f

// ---------------- scratch (static device globals; no allocation) -------------
__device__ float g_hn[(size_t)BATCH * CCH * NTOK];          // 16 MB groupnorm out
__device__ float g_qkv[(size_t)BATCH * 3 * CCH * NTOK];     // 50 MB qkv
__device__ float g_attn[(size_t)BATCH * NH * NTOK * NTOK];  // 1 GB attention scores
__device__ float g_aoT[(size_t)BATCH * NTOK * CCH];         // 16 MB attn out, [b][n][c]

// ---------------- GroupNorm (vectorized) --------------------------------------
__global__ void groupnorm_kernel(const float* __restrict__ x,
                                 const float* __restrict__ w,
                                 const float* __restrict__ b) {
    const int CPG = CCH / GROUPS;  // 16
    int bb = blockIdx.x / GROUPS;
    int g  = blockIdx.x % GROUPS;
    const float4* xp = (const float4*)(x + ((size_t)bb * CCH + (size_t)g * CPG) * NTOK);
    float4* hp = (float4*)(g_hn + ((size_t)bb * CCH + (size_t)g * CPG) * NTOK);
    int tid = threadIdx.x;
    const int TOT4 = CPG * NTOK / 4;  // 16384 float4

    float s = 0.f, s2 = 0.f;
    for (int i = tid; i < TOT4; i += 256) {
        float4 v = xp[i];
        s += v.x + v.y + v.z + v.w;
        s2 += v.x * v.x + v.y * v.y + v.z * v.z + v.w * v.w;
    }
    __shared__ float sh[256], sh2[256];
    sh[tid] = s; sh2[tid] = s2;
    __syncthreads();
    for (int o = 128; o > 0; o >>= 1) {
        if (tid < o) { sh[tid] += sh[tid + o]; sh2[tid] += sh2[tid + o]; }
        __syncthreads();
    }
    float mean = sh[0] / (CPG * NTOK);
    float var  = sh2[0] / (CPG * NTOK) - mean * mean;
    float inv  = rsqrtf(var + EPS);

    for (int i = tid; i < TOT4; i += 256) {
        int ch = g * CPG + (i >> 10);  // i*4/4096
        float sc = inv * w[ch];
        float off = b[ch] - mean * sc;
        float4 v = xp[i];
        v.x = v.x * sc + off; v.y = v.y * sc + off;
        v.z = v.z * sc + off; v.w = v.w * sc + off;
        hp[i] = v;
    }
}

// ---------------- 128x128 register-blocked SGEMM ------------------------------
// C[m,n] = alpha * sum_k A[m,k]*B[k,n] (+bias[m]) (+resid[m,n])
// TA: A stored K x M, else M x K.  TB: B stored N x K, else K x N.
// Requires M%128==0, N%128==0, K%8==0, all lds %4==0.
template <bool TA, bool TB>
__global__ void __launch_bounds__(256, 2)
sgemm128(const float* __restrict__ A, const float* __restrict__ B,
         float* __restrict__ C,
         int K, int lda, int ldb, int ldc,
         size_t sA, size_t sB, size_t sC,
         float alpha, const float* __restrict__ bias,
         const float* __restrict__ resid, size_t sR) {
    A += (size_t)blockIdx.z * sA;
    B += (size_t)blockIdx.z * sB;
    C += (size_t)blockIdx.z * sC;
    if (resid) resid += (size_t)blockIdx.z * sR;

    const int tid = threadIdx.x;
    const int tx = tid & 15;   // n dir
    const int ty = tid >> 4;   // m dir
    const int row0 = blockIdx.y * 128;
    const int col0 = blockIdx.x * 128;

    __shared__ float As[8][128];
    __shared__ float Bs[8][128];

    // global load pointers
    const float* Ab;
    int am, akq, ak, am4;
    if (!TA) {
        am = tid >> 1; akq = (tid & 1) * 4;
        Ab = A + (size_t)(row0 + am) * lda + akq;
    } else {
        ak = tid >> 5; am4 = (tid & 31) * 4;
        Ab = A + (size_t)ak * lda + row0 + am4;
    }
    const float* Bb;
    int bn, bkq, bk, bn4;
    if (!TB) {
        bk = tid >> 5; bn4 = (tid & 31) * 4;
        Bb = B + (size_t)bk * ldb + col0 + bn4;
    } else {
        bn = tid >> 1; bkq = (tid & 1) * 4;
        Bb = B + (size_t)(col0 + bn) * ldb + bkq;
    }

    float acc[8][8];
#pragma unroll
    for (int i = 0; i < 8; i++)
#pragma unroll
        for (int j = 0; j < 8; j++) acc[i][j] = 0.f;

    float4 pa, pb;
    // first tile loads
    pa = TA ? *(const float4*)(Ab) : *(const float4*)(Ab);
    // (same expression; separate index math baked into Ab)
    pb = *(const float4*)(Bb);

    for (int k0 = 0; k0 < K; k0 += 8) {
        // store prefetched tile
        if (!TA) {
            As[akq + 0][am] = pa.x; As[akq + 1][am] = pa.y;
            As[akq + 2][am] = pa.z; As[akq + 3][am] = pa.w;
        } else {
            *(float4*)&As[ak][am4] = pa;
        }
        if (!TB) {
            *(float4*)&Bs[bk][bn4] = pb;
        } else {
            Bs[bkq + 0][bn] = pb.x; Bs[bkq + 1][bn] = pb.y;
            Bs[bkq + 2][bn] = pb.z; Bs[bkq + 3][bn] = pb.w;
        }
        __syncthreads();

        if (k0 + 8 < K) {
            int kn = k0 + 8;
            pa = TA ? *(const float4*)(Ab + (size_t)kn * lda)
                    : *(const float4*)(Ab + kn);
            pb = TB ? *(const float4*)(Bb + kn)
                    : *(const float4*)(Bb + (size_t)kn * ldb);
        }

#pragma unroll
        for (int k = 0; k < 8; k++) {
            float ar[8], br[8];
            float4 a0 = *(float4*)&As[k][ty * 4];
            float4 a1 = *(float4*)&As[k][64 + ty * 4];
            float4 b0 = *(float4*)&Bs[k][tx * 4];
            float4 b1 = *(float4*)&Bs[k][64 + tx * 4];
            ar[0] = a0.x; ar[1] = a0.y; ar[2] = a0.z; ar[3] = a0.w;
            ar[4] = a1.x; ar[5] = a1.y; ar[6] = a1.z; ar[7] = a1.w;
            br[0] = b0.x; br[1] = b0.y; br[2] = b0.z; br[3] = b0.w;
            br[4] = b1.x; br[5] = b1.y; br[6] = b1.z; br[7] = b1.w;
#pragma unroll
            for (int i = 0; i < 8; i++)
#pragma unroll
                for (int j = 0; j < 8; j++)
                    acc[i][j] = fmaf(ar[i], br[j], acc[i][j]);
        }
        __syncthreads();
    }

#pragma unroll
    for (int i = 0; i < 8; i++) {
        int m = row0 + ((i < 4) ? (ty * 4 + i) : (64 + ty * 4 + i - 4));
        float bi = bias ? bias[m] : 0.f;
#pragma unroll
        for (int j = 0; j < 8; j++) {
            int n = col0 + ((j < 4) ? (tx * 4 + j) : (64 + tx * 4 + j - 4));
            float v = acc[i][j] * alpha + bi;
            if (resid) v += resid[(size_t)m * ldc + n];
            C[(size_t)m * ldc + n] = v;
        }
    }
}

// ---------------- AV GEMM: aoT[n, c=h*64+d] = sum_m attn_h[n,m] v_h[d,m] ------
// 128(n) x 64(d) tile. A = attn (n x m row-major, lda=NTOK), B = v ([d][m], ldb=NTOK)
__global__ void __launch_bounds__(256, 2)
av_gemm(const float* __restrict__ attn, const float* __restrict__ v,
        float* __restrict__ aoT) {
    const int h = blockIdx.z;
    const float* A = attn + (size_t)h * NTOK * NTOK;
    const float* B = v + (size_t)h * HD * NTOK;
    float* C = aoT + (size_t)h * HD;  // column offset h*64 in width-512 matrix

    const int tid = threadIdx.x;
    const int tx = tid & 15;   // d dir (4 cols each)
    const int ty = tid >> 4;   // n dir (8 rows, split 4+4)
    const int row0 = blockIdx.x * 128;

    __shared__ float As[8][128];
    __shared__ float Bs[8][64];

    const int am = tid >> 1, akq = (tid & 1) * 4;
    const float* Ab = A + (size_t)(row0 + am) * NTOK + akq;
    const int bn = tid & 63, bkq = (tid >> 6) * 2;
    const float* Bb = B + (size_t)bn * NTOK + bkq;

    float acc[8][4];
#pragma unroll
    for (int i = 0; i < 8; i++)
#pragma unroll
        for (int j = 0; j < 4; j++) acc[i][j] = 0.f;

    float4 pa = *(const float4*)(Ab);
    float2 pb = *(const float2*)(Bb);

    for (int k0 = 0; k0 < NTOK; k0 += 8) {
        As[akq + 0][am] = pa.x; As[akq + 1][am] = pa.y;
        As[akq + 2][am] = pa.z; As[akq + 3][am] = pa.w;
        Bs[bkq + 0][bn] = pb.x; Bs[bkq + 1][bn] = pb.y;
        __syncthreads();

        if (k0 + 8 < NTOK) {
            pa = *(const float4*)(Ab + k0 + 8);
            pb = *(const float2*)(Bb + k0 + 8);
        }

#pragma unroll
        for (int k = 0; k < 8; k++) {
            float ar[8];
            float4 a0 = *(float4*)&As[k][ty * 4];
            float4 a1 = *(float4*)&As[k][64 + ty * 4];
            float4 b0 = *(float4*)&Bs[k][tx * 4];
            ar[0] = a0.x; ar[1] = a0.y; ar[2] = a0.z; ar[3] = a0.w;
            ar[4] = a1.x; ar[5] = a1.y; ar[6] = a1.z; ar[7] = a1.w;
            float br[4] = {b0.x, b0.y, b0.z, b0.w};
#pragma unroll
            for (int i = 0; i < 8; i++)
#pragma unroll
                for (int j = 0; j < 4; j++)
                    acc[i][j] = fmaf(ar[i], br[j], acc[i][j]);
        }
        __syncthreads();
    }

#pragma unroll
    for (int i = 0; i < 8; i++) {
        int n = row0 + ((i < 4) ? (ty * 4 + i) : (64 + ty * 4 + i - 4));
#pragma unroll
        for (int j = 0; j < 4; j++) {
            C[(size_t)n * CCH + tx * 4 + j] = acc[i][j];
        }
    }
}

// ---------------- softmax over last dim (4096), in place, vectorized ----------
__global__ void softmax_kernel(float* __restrict__ attn) {
    float4* p = (float4*)(attn + (size_t)blockIdx.x * NTOK);
    int tid = threadIdx.x;  // 256
    float4 vals[4];
    float mx = -INFINITY;
#pragma unroll
    for (int i = 0; i < 4; i++) {
        vals[i] = p[tid + i * 256];
        mx = fmaxf(mx, fmaxf(fmaxf(vals[i].x, vals[i].y), fmaxf(vals[i].z, vals[i].w)));
    }
    __shared__ float sh[256];
    sh[tid] = mx;
    __syncthreads();
    for (int o = 128; o > 0; o >>= 1) {
        if (tid < o) sh[tid] = fmaxf(sh[tid], sh[tid + o]);
        __syncthreads();
    }
    mx = sh[0];
    __syncthreads();
    float s = 0.f;
#pragma unroll
    for (int i = 0; i < 4; i++) {
        vals[i].x = __expf(vals[i].x - mx); vals[i].y = __expf(vals[i].y - mx);
        vals[i].z = __expf(vals[i].z - mx); vals[i].w = __expf(vals[i].w - mx);
        s += vals[i].x + vals[i].y + vals[i].z + vals[i].w;
    }
    sh[tid] = s;
    __syncthreads();
    for (int o = 128; o > 0; o >>= 1) {
        if (tid < o) sh[tid] += sh[tid + o];
        __syncthreads();
    }
    float inv = 1.0f / sh[0];
#pragma unroll
    for (int i = 0; i < 4; i++) {
        vals[i].x *= inv; vals[i].y *= inv; vals[i].z *= inv; vals[i].w *= inv;
        p[tid + i * 256] = vals[i];
    }
}

// ---------------- launch ------------------------------------------------------
extern "C" void kernel_launch(void* const* d_in, const int* in_sizes, int n_in,
                              void* d_out, int out_size) {
    const float* x      = (const float*)d_in[0];
    const float* norm_w = (const float*)d_in[1];
    const float* norm_b = (const float*)d_in[2];
    const float* qkv_w  = (const float*)d_in[3];
    const float* qkv_b  = (const float*)d_in[4];
    const float* proj_w = (const float*)d_in[5];
    const float* proj_b = (const float*)d_in[6];
    float* out = (float*)d_out;

    float *hn, *qkv, *attn, *aoT;
    cudaGetSymbolAddress((void**)&hn,   g_hn);
    cudaGetSymbolAddress((void**)&qkv,  g_qkv);
    cudaGetSymbolAddress((void**)&attn, g_attn);
    cudaGetSymbolAddress((void**)&aoT,  g_aoT);

    const size_t CN  = (size_t)CCH * NTOK;
    const size_t HDN = (size_t)HD * NTOK;
    const size_t NN  = (size_t)NTOK * NTOK;

    // 1) GroupNorm
    groupnorm_kernel<<<BATCH * GROUPS, 256>>>(x, norm_w, norm_b);

    // 2) QKV GEMM: [1536,512] x [512,4096] per batch
    sgemm128<false, false><<<dim3(NTOK / 128, (3 * CCH) / 128, BATCH), 256>>>(
        qkv_w, hn, qkv,
        CCH, CCH, NTOK, NTOK,
        (size_t)0, CN, 3 * CN,
        1.0f, qkv_b, nullptr, 0);

    // 3) scores: attn[n,m] = 0.125 * sum_d q[d,n] k[d,m]   (z = head)
    for (int b = 0; b < BATCH; b++) {
        const float* qb = qkv + (size_t)b * 3 * CN;
        const float* kb = qkv + (size_t)b * 3 * CN + CN;
        float* ab = attn + (size_t)b * NH * NN;
        sgemm128<true, false><<<dim3(NTOK / 128, NTOK / 128, NH), 256>>>(
            qb, kb, ab,
            HD, NTOK, NTOK, NTOK,
            HDN, HDN, NN,
            0.125f, nullptr, nullptr, 0);
    }

    // 4) softmax rows
    softmax_kernel<<<BATCH * NH * NTOK, 256>>>(attn);

    // 5) AV: aoT[b][n][h*64+d]
    for (int b = 0; b < BATCH; b++) {
        const float* vb = qkv + (size_t)b * 3 * CN + 2 * CN;
        const float* ab = attn + (size_t)b * NH * NN;
        float* ob = aoT + (size_t)b * CN;
        av_gemm<<<dim3(NTOK / 128, 1, NH), 256>>>(ab, vb, ob);
    }

    // 6) proj + bias + residual: out[o,n] = proj_w @ aoT^T + proj_b + x
    sgemm128<false, true><<<dim3(NTOK / 128, CCH / 128, BATCH), 256>>>(
        proj_w, aoT, out,
        CCH, CCH, CCH, NTOK,
        (size_t)0, CN, CN,
        1.0f, proj_b, x, CN);
}

// round 3
// speedup vs baseline: 4.3162x; 2.5004x over previous
#include <cuda_runtime.h>
#include <math.h>
#include <stdint.h>

#define BATCH 2
#define CCH 512
#define NH 8
#define HD 64
#define GROUPS 32
#define NTOK 4096
#define EPS 1e-5f

// ---------------- scratch (static device globals; no allocation) -------------
__device__ float g_hn[(size_t)BATCH * CCH * NTOK];       // 16 MB groupnorm out
__device__ float g_qkv[(size_t)BATCH * 3 * CCH * NTOK];  // 50 MB qkv
__device__ float g_aoT[(size_t)BATCH * NTOK * CCH];      // 16 MB attn out, [b][n][c]

// ---------------- helpers -----------------------------------------------------
__device__ __forceinline__ uint32_t f2tf32(float f) {
    uint32_t u;
    asm("cvt.rna.tf32.f32 %0, %1;" : "=r"(u) : "f"(f));
    return u;
}

__device__ __forceinline__ void mma_tf32(float c[4], const uint32_t a[4],
                                         uint32_t b0, uint32_t b1) {
    asm volatile(
        "mma.sync.aligned.m16n8k8.row.col.f32.tf32.tf32.f32 "
        "{%0,%1,%2,%3}, {%4,%5,%6,%7}, {%8,%9}, {%0,%1,%2,%3};\n"
        : "+f"(c[0]), "+f"(c[1]), "+f"(c[2]), "+f"(c[3])
        : "r"(a[0]), "r"(a[1]), "r"(a[2]), "r"(a[3]), "r"(b0), "r"(b1));
}

// ---------------- GroupNorm (vectorized) --------------------------------------
__global__ void groupnorm_kernel(const float* __restrict__ x,
                                 const float* __restrict__ w,
                                 const float* __restrict__ b) {
    const int CPG = CCH / GROUPS;  // 16
    int bb = blockIdx.x / GROUPS;
    int g  = blockIdx.x % GROUPS;
    const float4* xp = (const float4*)(x + ((size_t)bb * CCH + (size_t)g * CPG) * NTOK);
    float4* hp = (float4*)(g_hn + ((size_t)bb * CCH + (size_t)g * CPG) * NTOK);
    int tid = threadIdx.x;
    const int TOT4 = CPG * NTOK / 4;

    float s = 0.f, s2 = 0.f;
    for (int i = tid; i < TOT4; i += 256) {
        float4 v = xp[i];
        s += v.x + v.y + v.z + v.w;
        s2 += v.x * v.x + v.y * v.y + v.z * v.z + v.w * v.w;
    }
    __shared__ float sh[256], sh2[256];
    sh[tid] = s; sh2[tid] = s2;
    __syncthreads();
    for (int o = 128; o > 0; o >>= 1) {
        if (tid < o) { sh[tid] += sh[tid + o]; sh2[tid] += sh2[tid + o]; }
        __syncthreads();
    }
    float mean = sh[0] / (CPG * NTOK);
    float var  = sh2[0] / (CPG * NTOK) - mean * mean;
    float inv  = rsqrtf(var + EPS);

    for (int i = tid; i < TOT4; i += 256) {
        int ch = g * CPG + (i >> 10);
        float sc = inv * w[ch];
        float off = b[ch] - mean * sc;
        float4 v = xp[i];
        v.x = v.x * sc + off; v.y = v.y * sc + off;
        v.z = v.z * sc + off; v.w = v.w * sc + off;
        hp[i] = v;
    }
}

// ---------------- 128x128 register-blocked SGEMM (fp32) -----------------------
template <bool TA, bool TB>
__global__ void __launch_bounds__(256, 2)
sgemm128(const float* __restrict__ A, const float* __restrict__ B,
         float* __restrict__ C,
         int K, int lda, int ldb, int ldc,
         size_t sA, size_t sB, size_t sC,
         float alpha, const float* __restrict__ bias,
         const float* __restrict__ resid, size_t sR) {
    A += (size_t)blockIdx.z * sA;
    B += (size_t)blockIdx.z * sB;
    C += (size_t)blockIdx.z * sC;
    if (resid) resid += (size_t)blockIdx.z * sR;

    const int tid = threadIdx.x;
    const int tx = tid & 15;
    const int ty = tid >> 4;
    const int row0 = blockIdx.y * 128;
    const int col0 = blockIdx.x * 128;

    __shared__ float As[8][128];
    __shared__ float Bs[8][128];

    const float* Ab;
    int am, akq, ak, am4;
    if (!TA) {
        am = tid >> 1; akq = (tid & 1) * 4;
        Ab = A + (size_t)(row0 + am) * lda + akq;
    } else {
        ak = tid >> 5; am4 = (tid & 31) * 4;
        Ab = A + (size_t)ak * lda + row0 + am4;
    }
    const float* Bb;
    int bn, bkq, bk, bn4;
    if (!TB) {
        bk = tid >> 5; bn4 = (tid & 31) * 4;
        Bb = B + (size_t)bk * ldb + col0 + bn4;
    } else {
        bn = tid >> 1; bkq = (tid & 1) * 4;
        Bb = B + (size_t)(col0 + bn) * ldb + bkq;
    }

    float acc[8][8];
#pragma unroll
    for (int i = 0; i < 8; i++)
#pragma unroll
        for (int j = 0; j < 8; j++) acc[i][j] = 0.f;

    float4 pa = *(const float4*)(Ab);
    float4 pb = *(const float4*)(Bb);

    for (int k0 = 0; k0 < K; k0 += 8) {
        if (!TA) {
            As[akq + 0][am] = pa.x; As[akq + 1][am] = pa.y;
            As[akq + 2][am] = pa.z; As[akq + 3][am] = pa.w;
        } else {
            *(float4*)&As[ak][am4] = pa;
        }
        if (!TB) {
            *(float4*)&Bs[bk][bn4] = pb;
        } else {
            Bs[bkq + 0][bn] = pb.x; Bs[bkq + 1][bn] = pb.y;
            Bs[bkq + 2][bn] = pb.z; Bs[bkq + 3][bn] = pb.w;
        }
        __syncthreads();

        if (k0 + 8 < K) {
            int kn = k0 + 8;
            pa = TA ? *(const float4*)(Ab + (size_t)kn * lda)
                    : *(const float4*)(Ab + kn);
            pb = TB ? *(const float4*)(Bb + kn)
                    : *(const float4*)(Bb + (size_t)kn * ldb);
        }

#pragma unroll
        for (int k = 0; k < 8; k++) {
            float ar[8], br[8];
            float4 a0 = *(float4*)&As[k][ty * 4];
            float4 a1 = *(float4*)&As[k][64 + ty * 4];
            float4 b0 = *(float4*)&Bs[k][tx * 4];
            float4 b1 = *(float4*)&Bs[k][64 + tx * 4];
            ar[0] = a0.x; ar[1] = a0.y; ar[2] = a0.z; ar[3] = a0.w;
            ar[4] = a1.x; ar[5] = a1.y; ar[6] = a1.z; ar[7] = a1.w;
            br[0] = b0.x; br[1] = b0.y; br[2] = b0.z; br[3] = b0.w;
            br[4] = b1.x; br[5] = b1.y; br[6] = b1.z; br[7] = b1.w;
#pragma unroll
            for (int i = 0; i < 8; i++)
#pragma unroll
                for (int j = 0; j < 8; j++)
                    acc[i][j] = fmaf(ar[i], br[j], acc[i][j]);
        }
        __syncthreads();
    }

#pragma unroll
    for (int i = 0; i < 8; i++) {
        int m = row0 + ((i < 4) ? (ty * 4 + i) : (64 + ty * 4 + i - 4));
        float bi = bias ? bias[m] : 0.f;
#pragma unroll
        for (int j = 0; j < 8; j++) {
            int n = col0 + ((j < 4) ? (tx * 4 + j) : (64 + tx * 4 + j - 4));
            float v = acc[i][j] * alpha + bi;
            if (resid) v += resid[(size_t)m * ldc + n];
            C[(size_t)m * ldc + n] = v;
        }
    }
}

// ---------------- fused flash attention (tf32 mma) ----------------------------
// grid: (NTOK/64, NH, BATCH), block: 128 threads (4 warps, 16 q-rows each).
// qkv layout: [b][3*C][n]; head h of q = rows h*64..h*64+63 of q section.
// output: aoT[b][n][h*64+d]  (token-major, channel contiguous)
#define SKV 68   // smem stride (conflict-considered, 16B-aligned rows)

__global__ void __launch_bounds__(128, 2)
flash_attn(const float* __restrict__ qkv, float* __restrict__ aoT) {
    extern __shared__ uint32_t dynsmem[];
    uint32_t* Ks = dynsmem;                         // [64 d][SKV] tf32 bits
    uint32_t* Vs = dynsmem + 64 * SKV;              // [64 d][SKV]
    const int tid = threadIdx.x;
    const int w = tid >> 5, lane = tid & 31;
    const int g = lane >> 2, tg = lane & 3;
    uint32_t* Ps = dynsmem + 2 * 64 * SKV + w * 16 * SKV;  // [16][SKV] per warp

    const int b = blockIdx.z, h = blockIdx.y;
    const size_t CN = (size_t)CCH * NTOK;
    const float* qg = qkv + (size_t)b * 3 * CN + (size_t)(h * HD) * NTOK;
    const float* kg = qg + CN;
    const float* vg = qg + 2 * CN;

    const int nq0 = blockIdx.x * 64 + w * 16;  // this warp's first q row

    // ---- preload Q fragments (scaled, tf32) ----
    uint32_t qa[8][4];
#pragma unroll
    for (int ks = 0; ks < 8; ks++) {
        int d0 = ks * 8;
        qa[ks][0] = f2tf32(qg[(size_t)(d0 + tg) * NTOK + nq0 + g] * 0.125f);
        qa[ks][1] = f2tf32(qg[(size_t)(d0 + tg) * NTOK + nq0 + g + 8] * 0.125f);
        qa[ks][2] = f2tf32(qg[(size_t)(d0 + tg + 4) * NTOK + nq0 + g] * 0.125f);
        qa[ks][3] = f2tf32(qg[(size_t)(d0 + tg + 4) * NTOK + nq0 + g + 8] * 0.125f);
    }

    float o[8][4];
#pragma unroll
    for (int i = 0; i < 8; i++)
#pragma unroll
        for (int j = 0; j < 4; j++) o[i][j] = 0.f;
    float m0 = -1e30f, m1 = -1e30f, l0 = 0.f, l1 = 0.f;

    for (int kt = 0; kt < NTOK / 64; kt++) {
        const int mt0 = kt * 64;
        __syncthreads();
        // cooperative K/V tile load -> smem (tf32-converted)
#pragma unroll
        for (int i = 0; i < 8; i++) {
            int e = tid + i * 128;       // 0..1023
            int row = e >> 4;            // d
            int c4 = (e & 15) * 4;       // m within tile
            float4 kf = *(const float4*)&kg[(size_t)row * NTOK + mt0 + c4];
            uint4 kt4;
            kt4.x = f2tf32(kf.x); kt4.y = f2tf32(kf.y);
            kt4.z = f2tf32(kf.z); kt4.w = f2tf32(kf.w);
            *(uint4*)&Ks[row * SKV + c4] = kt4;
            float4 vf = *(const float4*)&vg[(size_t)row * NTOK + mt0 + c4];
            uint4 vt4;
            vt4.x = f2tf32(vf.x); vt4.y = f2tf32(vf.y);
            vt4.z = f2tf32(vf.z); vt4.w = f2tf32(vf.w);
            *(uint4*)&Vs[row * SKV + c4] = vt4;
        }
        __syncthreads();

        // ---- S = (Q*scale)^T K : per warp 16 x 64 ----
        float c[8][4];
#pragma unroll
        for (int nt = 0; nt < 8; nt++) {
            c[nt][0] = c[nt][1] = c[nt][2] = c[nt][3] = 0.f;
#pragma unroll
            for (int ks = 0; ks < 8; ks++) {
                uint32_t b0 = Ks[(ks * 8 + tg) * SKV + nt * 8 + g];
                uint32_t b1 = Ks[(ks * 8 + tg + 4) * SKV + nt * 8 + g];
                mma_tf32(c[nt], qa[ks], b0, b1);
            }
        }

        // ---- online softmax ----
        float tm0 = -1e30f, tm1 = -1e30f;
#pragma unroll
        for (int nt = 0; nt < 8; nt++) {
            tm0 = fmaxf(tm0, fmaxf(c[nt][0], c[nt][1]));
            tm1 = fmaxf(tm1, fmaxf(c[nt][2], c[nt][3]));
        }
        tm0 = fmaxf(tm0, __shfl_xor_sync(0xffffffffu, tm0, 1));
        tm0 = fmaxf(tm0, __shfl_xor_sync(0xffffffffu, tm0, 2));
        tm1 = fmaxf(tm1, __shfl_xor_sync(0xffffffffu, tm1, 1));
        tm1 = fmaxf(tm1, __shfl_xor_sync(0xffffffffu, tm1, 2));
        float nm0 = fmaxf(m0, tm0), nm1 = fmaxf(m1, tm1);
        float a0 = __expf(m0 - nm0), a1 = __expf(m1 - nm1);
        m0 = nm0; m1 = nm1;
        float s0 = 0.f, s1 = 0.f;
#pragma unroll
        for (int nt = 0; nt < 8; nt++) {
            c[nt][0] = __expf(c[nt][0] - nm0);
            c[nt][1] = __expf(c[nt][1] - nm0);
            c[nt][2] = __expf(c[nt][2] - nm1);
            c[nt][3] = __expf(c[nt][3] - nm1);
            s0 += c[nt][0] + c[nt][1];
            s1 += c[nt][2] + c[nt][3];
        }
        s0 += __shfl_xor_sync(0xffffffffu, s0, 1);
        s0 += __shfl_xor_sync(0xffffffffu, s0, 2);
        s1 += __shfl_xor_sync(0xffffffffu, s1, 1);
        s1 += __shfl_xor_sync(0xffffffffu, s1, 2);
        l0 = l0 * a0 + s0;
        l1 = l1 * a1 + s1;
#pragma unroll
        for (int nt = 0; nt < 8; nt++) {
            o[nt][0] *= a0; o[nt][1] *= a0;
            o[nt][2] *= a1; o[nt][3] *= a1;
        }

        // ---- P -> smem (per-warp region, tf32) ----
#pragma unroll
        for (int nt = 0; nt < 8; nt++) {
            Ps[g * SKV + nt * 8 + tg * 2]           = f2tf32(c[nt][0]);
            Ps[g * SKV + nt * 8 + tg * 2 + 1]       = f2tf32(c[nt][1]);
            Ps[(g + 8) * SKV + nt * 8 + tg * 2]     = f2tf32(c[nt][2]);
            Ps[(g + 8) * SKV + nt * 8 + tg * 2 + 1] = f2tf32(c[nt][3]);
        }
        __syncwarp();

        // ---- O += P @ V^T  (A = P[16 x 64m], B = V^T[m x d]) ----
#pragma unroll
        for (int ks = 0; ks < 8; ks++) {
            uint32_t pa[4];
            pa[0] = Ps[g * SKV + ks * 8 + tg];
            pa[1] = Ps[(g + 8) * SKV + ks * 8 + tg];
            pa[2] = Ps[g * SKV + ks * 8 + tg + 4];
            pa[3] = Ps[(g + 8) * SKV + ks * 8 + tg + 4];
#pragma unroll
            for (int nt = 0; nt < 8; nt++) {
                uint32_t b0 = Vs[(nt * 8 + g) * SKV + ks * 8 + tg];
                uint32_t b1 = Vs[(nt * 8 + g) * SKV + ks * 8 + tg + 4];
                mma_tf32(o[nt], pa, b0, b1);
            }
        }
        __syncwarp();
    }

    // ---- epilogue: divide by l, write aoT[n][h*64+d] ----
    float inv0 = 1.f / l0, inv1 = 1.f / l1;
    float* outp = aoT + (size_t)b * CN + (size_t)(h * HD);
#pragma unroll
    for (int nt = 0; nt < 8; nt++) {
        float2 r0 = make_float2(o[nt][0] * inv0, o[nt][1] * inv0);
        float2 r1 = make_float2(o[nt][2] * inv1, o[nt][3] * inv1);
        *(float2*)&outp[(size_t)(nq0 + g) * CCH + nt * 8 + tg * 2] = r0;
        *(float2*)&outp[(size_t)(nq0 + g + 8) * CCH + nt * 8 + tg * 2] = r1;
    }
}

// ---------------- launch ------------------------------------------------------
extern "C" void kernel_launch(void* const* d_in, const int* in_sizes, int n_in,
                              void* d_out, int out_size) {
    const float* x      = (const float*)d_in[0];
    const float* norm_w = (const float*)d_in[1];
    const float* norm_b = (const float*)d_in[2];
    const float* qkv_w  = (const float*)d_in[3];
    const float* qkv_b  = (const float*)d_in[4];
    const float* proj_w = (const float*)d_in[5];
    const float* proj_b = (const float*)d_in[6];
    float* out = (float*)d_out;

    float *hn, *qkv, *aoT;
    cudaGetSymbolAddress((void**)&hn,  g_hn);
    cudaGetSymbolAddress((void**)&qkv, g_qkv);
    cudaGetSymbolAddress((void**)&aoT, g_aoT);

    const size_t CN = (size_t)CCH * NTOK;

    // 1) GroupNorm
    groupnorm_kernel<<<BATCH * GROUPS, 256>>>(x, norm_w, norm_b);

    // 2) QKV GEMM: [1536,512] x [512,4096] per batch
    sgemm128<false, false><<<dim3(NTOK / 128, (3 * CCH) / 128, BATCH), 256>>>(
        qkv_w, hn, qkv,
        CCH, CCH, NTOK, NTOK,
        (size_t)0, CN, 3 * CN,
        1.0f, qkv_b, nullptr, 0);

    // 3) fused attention (QK^T + softmax + AV), tf32 tensor cores
    const int FA_SMEM = (2 * 64 * SKV + 4 * 16 * SKV) * 4;  // 52224 B
    static int fa_attr_set = 0;
    if (!fa_attr_set) {
        cudaFuncSetAttribute(flash_attn,
                             cudaFuncAttributeMaxDynamicSharedMemorySize, FA_SMEM);
        fa_attr_set = 1;
    }
    flash_attn<<<dim3(NTOK / 64, NH, BATCH), 128, FA_SMEM>>>(qkv, aoT);

    // 4) proj + bias + residual: out[o,n] = proj_w @ aoT^T + proj_b + x
    sgemm128<false, true><<<dim3(NTOK / 128, CCH / 128, BATCH), 256>>>(
        proj_w, aoT, out,
        CCH, CCH, CCH, NTOK,
        (size_t)0, CN, CN,
        1.0f, proj_b, x, CN);
}

// round 4
// speedup vs baseline: 5.3459x; 1.2386x over previous
#include <cuda_runtime.h>
#include <math.h>
#include <stdint.h>

#define BATCH 2
#define CCH 512
#define NH 8
#define HD 64
#define GROUPS 32
#define NTOK 4096
#define EPS 1e-5f

// ---------------- scratch (static device globals; no allocation) -------------
__device__ float g_hn[(size_t)BATCH * CCH * NTOK];       // 16 MB groupnorm out
__device__ float g_qkv[(size_t)BATCH * 3 * CCH * NTOK];  // 50 MB qkv
__device__ float g_aoT[(size_t)BATCH * NTOK * CCH];      // 16 MB attn out [b][n][c]

// ---------------- helpers -----------------------------------------------------
__device__ __forceinline__ uint32_t f2tf32(float f) {
    uint32_t u;
    asm("cvt.rna.tf32.f32 %0, %1;" : "=r"(u) : "f"(f));
    return u;
}

__device__ __forceinline__ void mma_tf32(float c[4], const uint32_t a[4],
                                         uint32_t b0, uint32_t b1) {
    asm volatile(
        "mma.sync.aligned.m16n8k8.row.col.f32.tf32.tf32.f32 "
        "{%0,%1,%2,%3}, {%4,%5,%6,%7}, {%8,%9}, {%0,%1,%2,%3};\n"
        : "+f"(c[0]), "+f"(c[1]), "+f"(c[2]), "+f"(c[3])
        : "r"(a[0]), "r"(a[1]), "r"(a[2]), "r"(a[3]), "r"(b0), "r"(b1));
}

// ---------------- GroupNorm (vectorized) --------------------------------------
__global__ void groupnorm_kernel(const float* __restrict__ x,
                                 const float* __restrict__ w,
                                 const float* __restrict__ b) {
    const int CPG = CCH / GROUPS;  // 16
    int bb = blockIdx.x / GROUPS;
    int g  = blockIdx.x % GROUPS;
    const float4* xp = (const float4*)(x + ((size_t)bb * CCH + (size_t)g * CPG) * NTOK);
    float4* hp = (float4*)(g_hn + ((size_t)bb * CCH + (size_t)g * CPG) * NTOK);
    int tid = threadIdx.x;
    const int TOT4 = CPG * NTOK / 4;

    float s = 0.f, s2 = 0.f;
    for (int i = tid; i < TOT4; i += 256) {
        float4 v = xp[i];
        s += v.x + v.y + v.z + v.w;
        s2 += v.x * v.x + v.y * v.y + v.z * v.z + v.w * v.w;
    }
    __shared__ float sh[256], sh2[256];
    sh[tid] = s; sh2[tid] = s2;
    __syncthreads();
    for (int o = 128; o > 0; o >>= 1) {
        if (tid < o) { sh[tid] += sh[tid + o]; sh2[tid] += sh2[tid + o]; }
        __syncthreads();
    }
    float mean = sh[0] / (CPG * NTOK);
    float var  = sh2[0] / (CPG * NTOK) - mean * mean;
    float inv  = rsqrtf(var + EPS);

    for (int i = tid; i < TOT4; i += 256) {
        int ch = g * CPG + (i >> 10);
        float sc = inv * w[ch];
        float off = b[ch] - mean * sc;
        float4 v = xp[i];
        v.x = v.x * sc + off; v.y = v.y * sc + off;
        v.z = v.z * sc + off; v.w = v.w * sc + off;
        hp[i] = v;
    }
}

// ---------------- tf32 tensor-core GEMM: 128x128x(BK=32) ----------------------
// C[m,n] = sum_k A[m,k]*B[k,n] + bias[m] (+resid[m,n])
// A global row-major [M][K] (lda=K typ). TBNK: B global [n][k] (ldb along k),
// else [k][n] (ldb along n). 256 threads, 8 warps (2m x 4n), each 64x32.
#define APAD 36
#define BPAD 136
template <bool TBNK>
__global__ void __launch_bounds__(256, 2)
gemm_tf32(const float* __restrict__ A, const float* __restrict__ B,
          float* __restrict__ C, int K, int lda, int ldb, int ldc,
          size_t sA, size_t sB, size_t sC,
          const float* __restrict__ bias,
          const float* __restrict__ resid, size_t sR) {
    A += (size_t)blockIdx.z * sA;
    B += (size_t)blockIdx.z * sB;
    C += (size_t)blockIdx.z * sC;
    if (resid) resid += (size_t)blockIdx.z * sR;

    __shared__ uint32_t As[128 * APAD];   // [m][k] tf32
    __shared__ uint32_t Bs[32 * BPAD];    // [k][n] tf32

    const int tid = threadIdx.x;
    const int w = tid >> 5, lane = tid & 31;
    const int g = lane >> 2, tg = lane & 3;
    const int wm = w >> 2, wn = w & 3;      // warp tile: 64(m) x 32(n)
    const int m0 = blockIdx.y * 128;
    const int n0 = blockIdx.x * 128;

    // global load indices
    int arow[4], acol[4];
#pragma unroll
    for (int i = 0; i < 4; i++) {
        int e = tid + i * 256;
        arow[i] = e >> 3; acol[i] = (e & 7) * 4;
    }
    int brow[4], bcol[4];
#pragma unroll
    for (int i = 0; i < 4; i++) {
        int e = tid + i * 256;
        if (!TBNK) { brow[i] = e >> 5; bcol[i] = (e & 31) * 4; }  // [k][n]
        else       { brow[i] = e >> 3; bcol[i] = (e & 7) * 4; }   // [n][k]
    }

    float acc[4][4][4];
#pragma unroll
    for (int mf = 0; mf < 4; mf++)
#pragma unroll
        for (int nf = 0; nf < 4; nf++)
#pragma unroll
            for (int r = 0; r < 4; r++) acc[mf][nf][r] = 0.f;

    float4 pa[4], pb[4];
#pragma unroll
    for (int i = 0; i < 4; i++)
        pa[i] = *(const float4*)&A[(size_t)(m0 + arow[i]) * lda + acol[i]];
#pragma unroll
    for (int i = 0; i < 4; i++)
        pb[i] = TBNK ? *(const float4*)&B[(size_t)(n0 + brow[i]) * ldb + bcol[i]]
                     : *(const float4*)&B[(size_t)brow[i] * ldb + n0 + bcol[i]];

    for (int k0 = 0; k0 < K; k0 += 32) {
#pragma unroll
        for (int i = 0; i < 4; i++) {
            uint4 t;
            t.x = f2tf32(pa[i].x); t.y = f2tf32(pa[i].y);
            t.z = f2tf32(pa[i].z); t.w = f2tf32(pa[i].w);
            *(uint4*)&As[arow[i] * APAD + acol[i]] = t;
        }
#pragma unroll
        for (int i = 0; i < 4; i++) {
            if (!TBNK) {
                uint4 t;
                t.x = f2tf32(pb[i].x); t.y = f2tf32(pb[i].y);
                t.z = f2tf32(pb[i].z); t.w = f2tf32(pb[i].w);
                *(uint4*)&Bs[brow[i] * BPAD + bcol[i]] = t;
            } else {
                Bs[(bcol[i] + 0) * BPAD + brow[i]] = f2tf32(pb[i].x);
                Bs[(bcol[i] + 1) * BPAD + brow[i]] = f2tf32(pb[i].y);
                Bs[(bcol[i] + 2) * BPAD + brow[i]] = f2tf32(pb[i].z);
                Bs[(bcol[i] + 3) * BPAD + brow[i]] = f2tf32(pb[i].w);
            }
        }
        __syncthreads();

        if (k0 + 32 < K) {
            int kn = k0 + 32;
#pragma unroll
            for (int i = 0; i < 4; i++)
                pa[i] = *(const float4*)&A[(size_t)(m0 + arow[i]) * lda + kn + acol[i]];
#pragma unroll
            for (int i = 0; i < 4; i++)
                pb[i] = TBNK ? *(const float4*)&B[(size_t)(n0 + brow[i]) * ldb + kn + bcol[i]]
                             : *(const float4*)&B[(size_t)(kn + brow[i]) * ldb + n0 + bcol[i]];
        }

#pragma unroll
        for (int kk = 0; kk < 4; kk++) {
            uint32_t af[4][4];
#pragma unroll
            for (int mf = 0; mf < 4; mf++) {
                int mr = wm * 64 + mf * 16 + g;
                af[mf][0] = As[mr * APAD + kk * 8 + tg];
                af[mf][1] = As[(mr + 8) * APAD + kk * 8 + tg];
                af[mf][2] = As[mr * APAD + kk * 8 + tg + 4];
                af[mf][3] = As[(mr + 8) * APAD + kk * 8 + tg + 4];
            }
#pragma unroll
            for (int nf = 0; nf < 4; nf++) {
                int nc = wn * 32 + nf * 8 + g;
                uint32_t b0 = Bs[(kk * 8 + tg) * BPAD + nc];
                uint32_t b1 = Bs[(kk * 8 + tg + 4) * BPAD + nc];
#pragma unroll
                for (int mf = 0; mf < 4; mf++)
                    mma_tf32(acc[mf][nf], af[mf], b0, b1);
            }
        }
        __syncthreads();
    }

    // epilogue
#pragma unroll
    for (int mf = 0; mf < 4; mf++) {
        int m = m0 + wm * 64 + mf * 16 + g;
        float bi0 = bias[m], bi1 = bias[m + 8];
#pragma unroll
        for (int nf = 0; nf < 4; nf++) {
            int n = n0 + wn * 32 + nf * 8 + tg * 2;
            float2 v0 = make_float2(acc[mf][nf][0] + bi0, acc[mf][nf][1] + bi0);
            float2 v1 = make_float2(acc[mf][nf][2] + bi1, acc[mf][nf][3] + bi1);
            if (resid) {
                float2 r0 = *(const float2*)&resid[(size_t)m * ldc + n];
                float2 r1 = *(const float2*)&resid[(size_t)(m + 8) * ldc + n];
                v0.x += r0.x; v0.y += r0.y; v1.x += r1.x; v1.y += r1.y;
            }
            *(float2*)&C[(size_t)m * ldc + n] = v0;
            *(float2*)&C[(size_t)(m + 8) * ldc + n] = v1;
        }
    }
}

// ---------------- fused flash attention (tf32 mma) ----------------------------
// grid: (NTOK/128, NH, BATCH), block: 256 threads (8 warps x 16 q-rows).
#define SKV 68

__global__ void __launch_bounds__(256, 2)
flash_attn(const float* __restrict__ qkv, float* __restrict__ aoT) {
    extern __shared__ uint32_t dynsmem[];
    uint32_t* Ks = dynsmem;              // [64 d][SKV]
    uint32_t* Vs = dynsmem + 64 * SKV;   // [64 d][SKV]
    const int tid = threadIdx.x;
    const int w = tid >> 5, lane = tid & 31;
    const int g = lane >> 2, tg = lane & 3;
    uint32_t* Ps = dynsmem + 2 * 64 * SKV + w * 16 * SKV;  // [16][SKV] per warp

    const int b = blockIdx.z, h = blockIdx.y;
    const size_t CN = (size_t)CCH * NTOK;
    const float* qg = qkv + (size_t)b * 3 * CN + (size_t)(h * HD) * NTOK;
    const float* kg = qg + CN;
    const float* vg = qg + 2 * CN;

    const int nq0 = blockIdx.x * 128 + w * 16;

    uint32_t qa[8][4];
#pragma unroll
    for (int ks = 0; ks < 8; ks++) {
        int d0 = ks * 8;
        qa[ks][0] = f2tf32(qg[(size_t)(d0 + tg) * NTOK + nq0 + g] * 0.125f);
        qa[ks][1] = f2tf32(qg[(size_t)(d0 + tg) * NTOK + nq0 + g + 8] * 0.125f);
        qa[ks][2] = f2tf32(qg[(size_t)(d0 + tg + 4) * NTOK + nq0 + g] * 0.125f);
        qa[ks][3] = f2tf32(qg[(size_t)(d0 + tg + 4) * NTOK + nq0 + g + 8] * 0.125f);
    }

    float o[8][4];
#pragma unroll
    for (int i = 0; i < 8; i++)
#pragma unroll
        for (int j = 0; j < 4; j++) o[i][j] = 0.f;
    float m0 = -1e30f, m1 = -1e30f, l0 = 0.f, l1 = 0.f;

    for (int kt = 0; kt < NTOK / 64; kt++) {
        const int mt0 = kt * 64;
        __syncthreads();
#pragma unroll
        for (int i = 0; i < 4; i++) {
            int e = tid + i * 256;
            int row = e >> 4;
            int c4 = (e & 15) * 4;
            float4 kf = *(const float4*)&kg[(size_t)row * NTOK + mt0 + c4];
            uint4 kt4;
            kt4.x = f2tf32(kf.x); kt4.y = f2tf32(kf.y);
            kt4.z = f2tf32(kf.z); kt4.w = f2tf32(kf.w);
            *(uint4*)&Ks[row * SKV + c4] = kt4;
            float4 vf = *(const float4*)&vg[(size_t)row * NTOK + mt0 + c4];
            uint4 vt4;
            vt4.x = f2tf32(vf.x); vt4.y = f2tf32(vf.y);
            vt4.z = f2tf32(vf.z); vt4.w = f2tf32(vf.w);
            *(uint4*)&Vs[row * SKV + c4] = vt4;
        }
        __syncthreads();

        // S = (Q*scale)^T K : 16 x 64 per warp
        float c[8][4];
#pragma unroll
        for (int nt = 0; nt < 8; nt++) {
            c[nt][0] = c[nt][1] = c[nt][2] = c[nt][3] = 0.f;
#pragma unroll
            for (int ks = 0; ks < 8; ks++) {
                uint32_t b0 = Ks[(ks * 8 + tg) * SKV + nt * 8 + g];
                uint32_t b1 = Ks[(ks * 8 + tg + 4) * SKV + nt * 8 + g];
                mma_tf32(c[nt], qa[ks], b0, b1);
            }
        }

        // online softmax
        float tm0 = -1e30f, tm1 = -1e30f;
#pragma unroll
        for (int nt = 0; nt < 8; nt++) {
            tm0 = fmaxf(tm0, fmaxf(c[nt][0], c[nt][1]));
            tm1 = fmaxf(tm1, fmaxf(c[nt][2], c[nt][3]));
        }
        tm0 = fmaxf(tm0, __shfl_xor_sync(0xffffffffu, tm0, 1));
        tm0 = fmaxf(tm0, __shfl_xor_sync(0xffffffffu, tm0, 2));
        tm1 = fmaxf(tm1, __shfl_xor_sync(0xffffffffu, tm1, 1));
        tm1 = fmaxf(tm1, __shfl_xor_sync(0xffffffffu, tm1, 2));
        float nm0 = fmaxf(m0, tm0), nm1 = fmaxf(m1, tm1);
        float a0 = __expf(m0 - nm0), a1 = __expf(m1 - nm1);
        m0 = nm0; m1 = nm1;
        float s0 = 0.f, s1 = 0.f;
#pragma unroll
        for (int nt = 0; nt < 8; nt++) {
            c[nt][0] = __expf(c[nt][0] - nm0);
            c[nt][1] = __expf(c[nt][1] - nm0);
            c[nt][2] = __expf(c[nt][2] - nm1);
            c[nt][3] = __expf(c[nt][3] - nm1);
            s0 += c[nt][0] + c[nt][1];
            s1 += c[nt][2] + c[nt][3];
        }
        s0 += __shfl_xor_sync(0xffffffffu, s0, 1);
        s0 += __shfl_xor_sync(0xffffffffu, s0, 2);
        s1 += __shfl_xor_sync(0xffffffffu, s1, 1);
        s1 += __shfl_xor_sync(0xffffffffu, s1, 2);
        l0 = l0 * a0 + s0;
        l1 = l1 * a1 + s1;
#pragma unroll
        for (int nt = 0; nt < 8; nt++) {
            o[nt][0] *= a0; o[nt][1] *= a0;
            o[nt][2] *= a1; o[nt][3] *= a1;
        }

        // P -> smem (tf32)
#pragma unroll
        for (int nt = 0; nt < 8; nt++) {
            Ps[g * SKV + nt * 8 + tg * 2]           = f2tf32(c[nt][0]);
            Ps[g * SKV + nt * 8 + tg * 2 + 1]       = f2tf32(c[nt][1]);
            Ps[(g + 8) * SKV + nt * 8 + tg * 2]     = f2tf32(c[nt][2]);
            Ps[(g + 8) * SKV + nt * 8 + tg * 2 + 1] = f2tf32(c[nt][3]);
        }
        __syncwarp();

        // O += P @ V^T
#pragma unroll
        for (int ks = 0; ks < 8; ks++) {
            uint32_t pa[4];
            pa[0] = Ps[g * SKV + ks * 8 + tg];
            pa[1] = Ps[(g + 8) * SKV + ks * 8 + tg];
            pa[2] = Ps[g * SKV + ks * 8 + tg + 4];
            pa[3] = Ps[(g + 8) * SKV + ks * 8 + tg + 4];
#pragma unroll
            for (int nt = 0; nt < 8; nt++) {
                uint32_t b0 = Vs[(nt * 8 + g) * SKV + ks * 8 + tg];
                uint32_t b1 = Vs[(nt * 8 + g) * SKV + ks * 8 + tg + 4];
                mma_tf32(o[nt], pa, b0, b1);
            }
        }
        __syncwarp();
    }

    float inv0 = 1.f / l0, inv1 = 1.f / l1;
    float* outp = aoT + (size_t)b * CN + (size_t)(h * HD);
#pragma unroll
    for (int nt = 0; nt < 8; nt++) {
        float2 r0 = make_float2(o[nt][0] * inv0, o[nt][1] * inv0);
        float2 r1 = make_float2(o[nt][2] * inv1, o[nt][3] * inv1);
        *(float2*)&outp[(size_t)(nq0 + g) * CCH + nt * 8 + tg * 2] = r0;
        *(float2*)&outp[(size_t)(nq0 + g + 8) * CCH + nt * 8 + tg * 2] = r1;
    }
}

// ---------------- launch ------------------------------------------------------
extern "C" void kernel_launch(void* const* d_in, const int* in_sizes, int n_in,
                              void* d_out, int out_size) {
    const float* x      = (const float*)d_in[0];
    const float* norm_w = (const float*)d_in[1];
    const float* norm_b = (const float*)d_in[2];
    const float* qkv_w  = (const float*)d_in[3];
    const float* qkv_b  = (const float*)d_in[4];
    const float* proj_w = (const float*)d_in[5];
    const float* proj_b = (const float*)d_in[6];
    float* out = (float*)d_out;

    float *hn, *qkv, *aoT;
    cudaGetSymbolAddress((void**)&hn,  g_hn);
    cudaGetSymbolAddress((void**)&qkv, g_qkv);
    cudaGetSymbolAddress((void**)&aoT, g_aoT);

    const size_t CN = (size_t)CCH * NTOK;

    // 1) GroupNorm
    groupnorm_kernel<<<BATCH * GROUPS, 256>>>(x, norm_w, norm_b);

    // 2) QKV GEMM (tf32 tensor cores): [1536,512] x [512,4096]
    gemm_tf32<false><<<dim3(NTOK / 128, (3 * CCH) / 128, BATCH), 256>>>(
        qkv_w, hn, qkv, CCH, CCH, NTOK, NTOK,
        (size_t)0, CN, 3 * CN, qkv_b, nullptr, 0);

    // 3) fused attention
    const int FA_SMEM = (2 * 64 * SKV + 8 * 16 * SKV) * 4;  // 69632 B
    cudaFuncSetAttribute(flash_attn,
                         cudaFuncAttributeMaxDynamicSharedMemorySize, FA_SMEM);
    flash_attn<<<dim3(NTOK / 128, NH, BATCH), 256, FA_SMEM>>>(qkv, aoT);

    // 4) proj (tf32) + bias + residual
    gemm_tf32<true><<<dim3(NTOK / 128, CCH / 128, BATCH), 256>>>(
        proj_w, aoT, out, CCH, CCH, CCH, NTOK,
        (size_t)0, CN, CN, proj_b, x, CN);
}

// round 5
// speedup vs baseline: 7.2376x; 1.3539x over previous
#include <cuda_runtime.h>
#include <cuda_bf16.h>
#include <math.h>
#include <stdint.h>

#define BATCH 2
#define CCH 512
#define NH 8
#define HD 64
#define GROUPS 32
#define NTOK 4096
#define EPS 1e-5f
#define LOG2E 1.44269504f

// ---------------- scratch (static device globals; no allocation) -------------
__device__ float g_hn[(size_t)BATCH * CCH * NTOK];                  // 16 MB
__device__ __nv_bfloat16 g_qkv[(size_t)BATCH * 3 * CCH * NTOK];     // 25 MB
__device__ __nv_bfloat16 g_aoT[(size_t)BATCH * NTOK * CCH];         // 8 MB [b][n][c]
__device__ float g_gnpart[BATCH * GROUPS][8][2];

// ---------------- helpers -----------------------------------------------------
__device__ __forceinline__ uint32_t packb(float lo, float hi) {
    __nv_bfloat162 t = __floats2bfloat162_rn(lo, hi);
    return *(uint32_t*)&t;
}
__device__ __forceinline__ float ex2f(float x) {
    float y;
    asm("ex2.approx.f32 %0, %1;" : "=f"(y) : "f"(x));
    return y;
}
__device__ __forceinline__ void mma_bf16(float c[4], const uint32_t a[4],
                                         uint32_t b0, uint32_t b1) {
    asm volatile(
        "mma.sync.aligned.m16n8k16.row.col.f32.bf16.bf16.f32 "
        "{%0,%1,%2,%3}, {%4,%5,%6,%7}, {%8,%9}, {%0,%1,%2,%3};\n"
        : "+f"(c[0]), "+f"(c[1]), "+f"(c[2]), "+f"(c[3])
        : "r"(a[0]), "r"(a[1]), "r"(a[2]), "r"(a[3]), "r"(b0), "r"(b1));
}

// ---------------- GroupNorm: stats + apply ------------------------------------
// grid (8 slices, BATCH*GROUPS). slice = 8192 elems = 2 channels.
__global__ void gn_stats(const float* __restrict__ x) {
    int bg = blockIdx.y, sl = blockIdx.x, tid = threadIdx.x;
    const float4* xp = (const float4*)x + (size_t)bg * 16384 + sl * 2048;
    float s = 0.f, s2 = 0.f;
    for (int i = tid; i < 2048; i += 256) {
        float4 v = xp[i];
        s += v.x + v.y + v.z + v.w;
        s2 += v.x * v.x + v.y * v.y + v.z * v.z + v.w * v.w;
    }
    __shared__ float sh[256], sh2[256];
    sh[tid] = s; sh2[tid] = s2;
    __syncthreads();
    for (int o = 128; o > 0; o >>= 1) {
        if (tid < o) { sh[tid] += sh[tid + o]; sh2[tid] += sh2[tid + o]; }
        __syncthreads();
    }
    if (tid == 0) {
        g_gnpart[bg][sl][0] = sh[0];
        g_gnpart[bg][sl][1] = sh2[0];
    }
}

__global__ void gn_apply(const float* __restrict__ x,
                         const float* __restrict__ w,
                         const float* __restrict__ b) {
    int bg = blockIdx.y, sl = blockIdx.x, tid = threadIdx.x;
    float S = 0.f, S2 = 0.f;
#pragma unroll
    for (int i = 0; i < 8; i++) {
        S += g_gnpart[bg][i][0];
        S2 += g_gnpart[bg][i][1];
    }
    float mean = S / 65536.f;
    float var  = S2 / 65536.f - mean * mean;
    float inv  = rsqrtf(var + EPS);
    int g = bg % GROUPS;
    const float4* xp = (const float4*)x + (size_t)bg * 16384 + sl * 2048;
    float4* hp = (float4*)g_hn + (size_t)bg * 16384 + sl * 2048;
    for (int i = tid; i < 2048; i += 256) {
        int ch = g * 16 + sl * 2 + (i >> 10);
        float sc = inv * w[ch];
        float off = b[ch] - mean * sc;
        float4 v = xp[i];
        v.x = v.x * sc + off; v.y = v.y * sc + off;
        v.z = v.z * sc + off; v.w = v.w * sc + off;
        hp[i] = v;
    }
}

// ---------------- bf16 tensor GEMM: 128x128, BK=32 ----------------------------
// C[m,n] = sum_k A[m,k]*B[k,n] + bias[m] (+resid)
// PROJ=false: B fp32 [k][n] (ldb=n-stride), C bf16.  (QKV)
// PROJ=true:  B bf16 [n][k] (ldb=k-stride), C fp32 + resid.  (proj)
template <bool PROJ>
__global__ void __launch_bounds__(256, 2)
gemm_bf16(const float* __restrict__ A, const void* __restrict__ Bv,
          void* __restrict__ Cv, int K, int lda, int ldb, int ldc,
          size_t sB, size_t sC,
          const float* __restrict__ bias,
          const float* __restrict__ resid, size_t sR) {
    __shared__ __nv_bfloat16 As[128][40];   // [m][k]
    __shared__ __nv_bfloat16 Bs[128][40];   // [n][k]

    const int tid = threadIdx.x;
    const int w = tid >> 5, lane = tid & 31;
    const int g = lane >> 2, tg = lane & 3;
    const int wm = w >> 2, wn = w & 3;      // warp tile 64m x 32n
    const int m0 = blockIdx.y * 128;
    const int n0 = blockIdx.x * 128;

    const float* Bf = (const float*)Bv + (PROJ ? 0 : (size_t)blockIdx.z * sB);
    const __nv_bfloat16* Bh = (const __nv_bfloat16*)Bv + (PROJ ? (size_t)blockIdx.z * sB : 0);
    float* Cf = (float*)Cv + (PROJ ? (size_t)blockIdx.z * sC : 0);
    __nv_bfloat16* Ch = (__nv_bfloat16*)Cv + (PROJ ? 0 : (size_t)blockIdx.z * sC);
    if (PROJ && resid) resid += (size_t)blockIdx.z * sR;

    // loader indices
    int am[4], ak[4];
#pragma unroll
    for (int i = 0; i < 4; i++) {
        int e = tid + i * 256;
        am[i] = e >> 3; ak[i] = (e & 7) * 4;
    }
    int bk0[4], bn0[4];
#pragma unroll
    for (int i = 0; i < 4; i++) {
        int e = tid + i * 256;
        if (!PROJ) { bk0[i] = e >> 5; bn0[i] = (e & 31) * 4; }  // fp32 [k][n]
        else       { bn0[i] = e >> 3; bk0[i] = (e & 7) * 4; }   // bf16 [n][k]
    }

    float acc[4][4][4];
#pragma unroll
    for (int mf = 0; mf < 4; mf++)
#pragma unroll
        for (int nf = 0; nf < 4; nf++)
#pragma unroll
            for (int r = 0; r < 4; r++) acc[mf][nf][r] = 0.f;

    float4 pa[4];
    float4 pbf[4];
    uint2  pbh[4];
#pragma unroll
    for (int i = 0; i < 4; i++)
        pa[i] = *(const float4*)&A[(size_t)(m0 + am[i]) * lda + ak[i]];
#pragma unroll
    for (int i = 0; i < 4; i++) {
        if (!PROJ) pbf[i] = *(const float4*)&Bf[(size_t)bk0[i] * ldb + n0 + bn0[i]];
        else       pbh[i] = *(const uint2*)&Bh[(size_t)(n0 + bn0[i]) * ldb + bk0[i]];
    }

    const uint32_t* As32 = (const uint32_t*)As;
    const uint32_t* Bs32 = (const uint32_t*)Bs;

    for (int k0 = 0; k0 < K; k0 += 32) {
#pragma unroll
        for (int i = 0; i < 4; i++) {
            uint2 t;
            t.x = packb(pa[i].x, pa[i].y);
            t.y = packb(pa[i].z, pa[i].w);
            *(uint2*)&As[am[i]][ak[i]] = t;
        }
#pragma unroll
        for (int i = 0; i < 4; i++) {
            if (!PROJ) {
                Bs[bn0[i] + 0][bk0[i]] = __float2bfloat16_rn(pbf[i].x);
                Bs[bn0[i] + 1][bk0[i]] = __float2bfloat16_rn(pbf[i].y);
                Bs[bn0[i] + 2][bk0[i]] = __float2bfloat16_rn(pbf[i].z);
                Bs[bn0[i] + 3][bk0[i]] = __float2bfloat16_rn(pbf[i].w);
            } else {
                *(uint2*)&Bs[bn0[i]][bk0[i]] = pbh[i];
            }
        }
        __syncthreads();

        if (k0 + 32 < K) {
            int kn = k0 + 32;
#pragma unroll
            for (int i = 0; i < 4; i++)
                pa[i] = *(const float4*)&A[(size_t)(m0 + am[i]) * lda + kn + ak[i]];
#pragma unroll
            for (int i = 0; i < 4; i++) {
                if (!PROJ) pbf[i] = *(const float4*)&Bf[(size_t)(kn + bk0[i]) * ldb + n0 + bn0[i]];
                else       pbh[i] = *(const uint2*)&Bh[(size_t)(n0 + bn0[i]) * ldb + kn + bk0[i]];
            }
        }

#pragma unroll
        for (int kc = 0; kc < 2; kc++) {
            uint32_t af[4][4];
#pragma unroll
            for (int mf = 0; mf < 4; mf++) {
                int mr = wm * 64 + mf * 16 + g;
                af[mf][0] = As32[mr * 20 + kc * 8 + tg];
                af[mf][1] = As32[(mr + 8) * 20 + kc * 8 + tg];
                af[mf][2] = As32[mr * 20 + kc * 8 + tg + 4];
                af[mf][3] = As32[(mr + 8) * 20 + kc * 8 + tg + 4];
            }
#pragma unroll
            for (int nf = 0; nf < 4; nf++) {
                int nc = wn * 32 + nf * 8 + g;
                uint32_t b0 = Bs32[nc * 20 + kc * 8 + tg];
                uint32_t b1 = Bs32[nc * 20 + kc * 8 + tg + 4];
#pragma unroll
                for (int mf = 0; mf < 4; mf++)
                    mma_bf16(acc[mf][nf], af[mf], b0, b1);
            }
        }
        __syncthreads();
    }

    // epilogue
#pragma unroll
    for (int mf = 0; mf < 4; mf++) {
        int m = m0 + wm * 64 + mf * 16 + g;
        float bi0 = bias[m], bi1 = bias[m + 8];
#pragma unroll
        for (int nf = 0; nf < 4; nf++) {
            int n = n0 + wn * 32 + nf * 8 + tg * 2;
            float v0 = acc[mf][nf][0] + bi0, v1 = acc[mf][nf][1] + bi0;
            float v2 = acc[mf][nf][2] + bi1, v3 = acc[mf][nf][3] + bi1;
            if (!PROJ) {
                *(uint32_t*)&Ch[(size_t)m * ldc + n] = packb(v0, v1);
                *(uint32_t*)&Ch[(size_t)(m + 8) * ldc + n] = packb(v2, v3);
            } else {
                float2 r0 = *(const float2*)&resid[(size_t)m * ldc + n];
                float2 r1 = *(const float2*)&resid[(size_t)(m + 8) * ldc + n];
                *(float2*)&Cf[(size_t)m * ldc + n] = make_float2(v0 + r0.x, v1 + r0.y);
                *(float2*)&Cf[(size_t)(m + 8) * ldc + n] = make_float2(v2 + r1.x, v3 + r1.y);
            }
        }
    }
}

// ---------------- fused flash attention (bf16 mma, FA2 register P) ------------
// grid (NTOK/128, NH, BATCH), 256 threads = 8 warps x 16 q-rows. kv tile = 64.
__global__ void __launch_bounds__(256, 2)
flash_attn(const __nv_bfloat16* __restrict__ qkv, __nv_bfloat16* __restrict__ aoT) {
    __shared__ __nv_bfloat16 Ksm[64][72];  // [m][d]
    __shared__ __nv_bfloat16 Vsm[64][72];  // [d][m]
    const int tid = threadIdx.x;
    const int w = tid >> 5, lane = tid & 31;
    const int g = lane >> 2, tg = lane & 3;

    const int b = blockIdx.z, h = blockIdx.y;
    const size_t CN = (size_t)CCH * NTOK;
    const __nv_bfloat16* qg = qkv + (size_t)b * 3 * CN + (size_t)(h * HD) * NTOK;
    const __nv_bfloat16* kg = qg + CN;
    const __nv_bfloat16* vg = qg + 2 * CN;

    const int nq0 = blockIdx.x * 128 + w * 16;

    // Q fragments: A[q][d] = Q[d][q], scaled by 0.125 (exact in bf16)
    uint32_t qa[4][4];
#pragma unroll
    for (int kc = 0; kc < 4; kc++) {
        int d0 = kc * 16 + 2 * tg;
#pragma unroll
        for (int rr = 0; rr < 2; rr++) {       // rows g, g+8 -> a0/a1 ; d+8 -> a2/a3
            int q = nq0 + g + rr * 8;
            float lo0 = __bfloat162float(qg[(size_t)d0 * NTOK + q]) * 0.125f;
            float hi0 = __bfloat162float(qg[(size_t)(d0 + 1) * NTOK + q]) * 0.125f;
            float lo8 = __bfloat162float(qg[(size_t)(d0 + 8) * NTOK + q]) * 0.125f;
            float hi8 = __bfloat162float(qg[(size_t)(d0 + 9) * NTOK + q]) * 0.125f;
            qa[kc][rr] = packb(lo0, hi0);
            qa[kc][rr + 2] = packb(lo8, hi8);
        }
    }

    float o[8][4];
#pragma unroll
    for (int i = 0; i < 8; i++)
#pragma unroll
        for (int j = 0; j < 4; j++) o[i][j] = 0.f;
    float m0 = -1e30f, m1 = -1e30f, l0 = 0.f, l1 = 0.f;

    const uint32_t* Ks32 = (const uint32_t*)Ksm;
    const uint32_t* Vs32 = (const uint32_t*)Vsm;

    for (int kt = 0; kt < NTOK / 64; kt++) {
        const int mt0 = kt * 64;
        __syncthreads();
        // load K (transpose to [m][d]) and V (copy, [d][m])
#pragma unroll
        for (int i = 0; i < 4; i++) {
            int e = tid + i * 256;
            int d = e >> 4;
            int m4 = (e & 15) * 4;
            uint2 kv = *(const uint2*)&kg[(size_t)d * NTOK + mt0 + m4];
            __nv_bfloat162 k01 = *(__nv_bfloat162*)&kv.x;
            __nv_bfloat162 k23 = *(__nv_bfloat162*)&kv.y;
            Ksm[m4 + 0][d] = k01.x;
            Ksm[m4 + 1][d] = k01.y;
            Ksm[m4 + 2][d] = k23.x;
            Ksm[m4 + 3][d] = k23.y;
            *(uint2*)&Vsm[d][m4] = *(const uint2*)&vg[(size_t)d * NTOK + mt0 + m4];
        }
        __syncthreads();

        // S = Q^T K : 16 x 64 per warp (logit units; q pre-scaled)
        float c[8][4];
#pragma unroll
        for (int nt = 0; nt < 8; nt++) {
            c[nt][0] = c[nt][1] = c[nt][2] = c[nt][3] = 0.f;
#pragma unroll
            for (int kc = 0; kc < 4; kc++) {
                uint32_t b0 = Ks32[(nt * 8 + g) * 36 + kc * 8 + tg];
                uint32_t b1 = Ks32[(nt * 8 + g) * 36 + kc * 8 + tg + 4];
                mma_bf16(c[nt], qa[kc], b0, b1);
            }
        }

        // online softmax (exp2 with log2e FMA)
        float tm0 = -1e30f, tm1 = -1e30f;
#pragma unroll
        for (int nt = 0; nt < 8; nt++) {
            tm0 = fmaxf(tm0, fmaxf(c[nt][0], c[nt][1]));
            tm1 = fmaxf(tm1, fmaxf(c[nt][2], c[nt][3]));
        }
        tm0 = fmaxf(tm0, __shfl_xor_sync(0xffffffffu, tm0, 1));
        tm0 = fmaxf(tm0, __shfl_xor_sync(0xffffffffu, tm0, 2));
        tm1 = fmaxf(tm1, __shfl_xor_sync(0xffffffffu, tm1, 1));
        tm1 = fmaxf(tm1, __shfl_xor_sync(0xffffffffu, tm1, 2));
        float nm0 = fmaxf(m0, tm0), nm1 = fmaxf(m1, tm1);
        float a0 = ex2f((m0 - nm0) * LOG2E), a1 = ex2f((m1 - nm1) * LOG2E);
        m0 = nm0; m1 = nm1;
        float nmL0 = nm0 * LOG2E, nmL1 = nm1 * LOG2E;
        float s0 = 0.f, s1 = 0.f;
#pragma unroll
        for (int nt = 0; nt < 8; nt++) {
            c[nt][0] = ex2f(fmaf(c[nt][0], LOG2E, -nmL0));
            c[nt][1] = ex2f(fmaf(c[nt][1], LOG2E, -nmL0));
            c[nt][2] = ex2f(fmaf(c[nt][2], LOG2E, -nmL1));
            c[nt][3] = ex2f(fmaf(c[nt][3], LOG2E, -nmL1));
            s0 += c[nt][0] + c[nt][1];
            s1 += c[nt][2] + c[nt][3];
        }
        s0 += __shfl_xor_sync(0xffffffffu, s0, 1);
        s0 += __shfl_xor_sync(0xffffffffu, s0, 2);
        s1 += __shfl_xor_sync(0xffffffffu, s1, 1);
        s1 += __shfl_xor_sync(0xffffffffu, s1, 2);
        l0 = l0 * a0 + s0;
        l1 = l1 * a1 + s1;
#pragma unroll
        for (int nt = 0; nt < 8; nt++) {
            o[nt][0] *= a0; o[nt][1] *= a0;
            o[nt][2] *= a1; o[nt][3] *= a1;
        }

        // pack P directly into A-fragments (no smem round-trip)
        uint32_t pa[4][4];
#pragma unroll
        for (int mc = 0; mc < 4; mc++) {
            pa[mc][0] = packb(c[2 * mc][0], c[2 * mc][1]);
            pa[mc][1] = packb(c[2 * mc][2], c[2 * mc][3]);
            pa[mc][2] = packb(c[2 * mc + 1][0], c[2 * mc + 1][1]);
            pa[mc][3] = packb(c[2 * mc + 1][2], c[2 * mc + 1][3]);
        }

        // O += P @ V^T
#pragma unroll
        for (int dt = 0; dt < 8; dt++) {
#pragma unroll
            for (int mc = 0; mc < 4; mc++) {
                uint32_t b0 = Vs32[(dt * 8 + g) * 36 + mc * 8 + tg];
                uint32_t b1 = Vs32[(dt * 8 + g) * 36 + mc * 8 + tg + 4];
                mma_bf16(o[dt], pa[mc], b0, b1);
            }
        }
    }

    // epilogue -> bf16 aoT[n][h*64+d]
    float inv0 = 1.f / l0, inv1 = 1.f / l1;
    __nv_bfloat16* outp = aoT + (size_t)b * CN + (size_t)(h * HD);
#pragma unroll
    for (int dt = 0; dt < 8; dt++) {
        *(uint32_t*)&outp[(size_t)(nq0 + g) * CCH + dt * 8 + tg * 2] =
            packb(o[dt][0] * inv0, o[dt][1] * inv0);
        *(uint32_t*)&outp[(size_t)(nq0 + g + 8) * CCH + dt * 8 + tg * 2] =
            packb(o[dt][2] * inv1, o[dt][3] * inv1);
    }
}

// ---------------- launch ------------------------------------------------------
extern "C" void kernel_launch(void* const* d_in, const int* in_sizes, int n_in,
                              void* d_out, int out_size) {
    const float* x      = (const float*)d_in[0];
    const float* norm_w = (const float*)d_in[1];
    const float* norm_b = (const float*)d_in[2];
    const float* qkv_w  = (const float*)d_in[3];
    const float* qkv_b  = (const float*)d_in[4];
    const float* proj_w = (const float*)d_in[5];
    const float* proj_b = (const float*)d_in[6];
    float* out = (float*)d_out;

    float* hn;
    __nv_bfloat16 *qkv, *aoT;
    cudaGetSymbolAddress((void**)&hn,  g_hn);
    cudaGetSymbolAddress((void**)&qkv, g_qkv);
    cudaGetSymbolAddress((void**)&aoT, g_aoT);

    const size_t CN = (size_t)CCH * NTOK;

    // 1) GroupNorm
    gn_stats<<<dim3(8, BATCH * GROUPS), 256>>>(x);
    gn_apply<<<dim3(8, BATCH * GROUPS), 256>>>(x, norm_w, norm_b);

    // 2) QKV GEMM (bf16 tensor): [1536,512] x [512,4096] -> bf16 qkv
    gemm_bf16<false><<<dim3(NTOK / 128, (3 * CCH) / 128, BATCH), 256>>>(
        qkv_w, hn, qkv, CCH, CCH, NTOK, NTOK,
        CN, 3 * CN, qkv_b, nullptr, 0);

    // 3) fused attention (bf16)
    flash_attn<<<dim3(NTOK / 128, NH, BATCH), 256>>>(qkv, aoT);

    // 4) proj (bf16 tensor) + bias + residual -> fp32 out
    gemm_bf16<true><<<dim3(NTOK / 128, CCH / 128, BATCH), 256>>>(
        proj_w, aoT, out, CCH, CCH, CCH, NTOK,
        CN, CN, proj_b, x, CN);
}

// round 6
// speedup vs baseline: 9.6903x; 1.3389x over previous
#include <cuda_runtime.h>
#include <cuda_bf16.h>
#include <math.h>
#include <stdint.h>

#define BATCH 2
#define CCH 512
#define NH 8
#define HD 64
#define GROUPS 32
#define NTOK 4096
#define EPS 1e-5f
#define LOG2E 1.44269504f

// ---------------- scratch (static device globals; no allocation) -------------
__device__ float g_hn[(size_t)BATCH * CCH * NTOK];                  // 16 MB
__device__ __nv_bfloat16 g_qkv[(size_t)BATCH * 3 * CCH * NTOK];     // 25 MB
__device__ __nv_bfloat16 g_aoT[(size_t)BATCH * NTOK * CCH];         // 8 MB [b][n][c]
__device__ float g_gnpart[BATCH * GROUPS][8][2];

// ---------------- helpers -----------------------------------------------------
__device__ __forceinline__ uint32_t packb(float lo, float hi) {
    __nv_bfloat162 t = __floats2bfloat162_rn(lo, hi);
    return *(uint32_t*)&t;
}
__device__ __forceinline__ float ex2f(float x) {
    float y;
    asm("ex2.approx.f32 %0, %1;" : "=f"(y) : "f"(x));
    return y;
}
__device__ __forceinline__ void mma_bf16(float c[4], const uint32_t a[4],
                                         uint32_t b0, uint32_t b1) {
    asm volatile(
        "mma.sync.aligned.m16n8k16.row.col.f32.bf16.bf16.f32 "
        "{%0,%1,%2,%3}, {%4,%5,%6,%7}, {%8,%9}, {%0,%1,%2,%3};\n"
        : "+f"(c[0]), "+f"(c[1]), "+f"(c[2]), "+f"(c[3])
        : "r"(a[0]), "r"(a[1]), "r"(a[2]), "r"(a[3]), "r"(b0), "r"(b1));
}
__device__ __forceinline__ void ldsm4t(uint32_t r[4], uint32_t addr) {
    asm volatile(
        "ldmatrix.sync.aligned.m8n8.x4.trans.shared.b16 {%0,%1,%2,%3}, [%4];"
        : "=r"(r[0]), "=r"(r[1]), "=r"(r[2]), "=r"(r[3]) : "r"(addr));
}
__device__ __forceinline__ void ldsm4(uint32_t r[4], uint32_t addr) {
    asm volatile(
        "ldmatrix.sync.aligned.m8n8.x4.shared.b16 {%0,%1,%2,%3}, [%4];"
        : "=r"(r[0]), "=r"(r[1]), "=r"(r[2]), "=r"(r[3]) : "r"(addr));
}

// ---------------- GroupNorm: stats + apply ------------------------------------
__global__ void gn_stats(const float* __restrict__ x) {
    int bg = blockIdx.y, sl = blockIdx.x, tid = threadIdx.x;
    const float4* xp = (const float4*)x + (size_t)bg * 16384 + sl * 2048;
    float s = 0.f, s2 = 0.f;
    for (int i = tid; i < 2048; i += 256) {
        float4 v = xp[i];
        s += v.x + v.y + v.z + v.w;
        s2 += v.x * v.x + v.y * v.y + v.z * v.z + v.w * v.w;
    }
    __shared__ float sh[256], sh2[256];
    sh[tid] = s; sh2[tid] = s2;
    __syncthreads();
    for (int o = 128; o > 0; o >>= 1) {
        if (tid < o) { sh[tid] += sh[tid + o]; sh2[tid] += sh2[tid + o]; }
        __syncthreads();
    }
    if (tid == 0) {
        g_gnpart[bg][sl][0] = sh[0];
        g_gnpart[bg][sl][1] = sh2[0];
    }
}

__global__ void gn_apply(const float* __restrict__ x,
                         const float* __restrict__ w,
                         const float* __restrict__ b) {
    int bg = blockIdx.y, sl = blockIdx.x, tid = threadIdx.x;
    float S = 0.f, S2 = 0.f;
#pragma unroll
    for (int i = 0; i < 8; i++) {
        S += g_gnpart[bg][i][0];
        S2 += g_gnpart[bg][i][1];
    }
    float mean = S / 65536.f;
    float var  = S2 / 65536.f - mean * mean;
    float inv  = rsqrtf(var + EPS);
    int g = bg % GROUPS;
    const float4* xp = (const float4*)x + (size_t)bg * 16384 + sl * 2048;
    float4* hp = (float4*)g_hn + (size_t)bg * 16384 + sl * 2048;
    for (int i = tid; i < 2048; i += 256) {
        int ch = g * 16 + sl * 2 + (i >> 10);
        float sc = inv * w[ch];
        float off = b[ch] - mean * sc;
        float4 v = xp[i];
        v.x = v.x * sc + off; v.y = v.y * sc + off;
        v.z = v.z * sc + off; v.w = v.w * sc + off;
        hp[i] = v;
    }
}

// ---------------- bf16 tensor GEMM: 128x128, BK=32 ----------------------------
template <bool PROJ>
__global__ void __launch_bounds__(256, 2)
gemm_bf16(const float* __restrict__ A, const void* __restrict__ Bv,
          void* __restrict__ Cv, int K, int lda, int ldb, int ldc,
          size_t sB, size_t sC,
          const float* __restrict__ bias,
          const float* __restrict__ resid, size_t sR) {
    __shared__ __nv_bfloat16 As[128][40];   // [m][k]
    __shared__ __nv_bfloat16 Bs[128][40];   // [n][k]

    const int tid = threadIdx.x;
    const int w = tid >> 5, lane = tid & 31;
    const int g = lane >> 2, tg = lane & 3;
    const int wm = w >> 2, wn = w & 3;
    const int m0 = blockIdx.y * 128;
    const int n0 = blockIdx.x * 128;

    const float* Bf = (const float*)Bv + (PROJ ? 0 : (size_t)blockIdx.z * sB);
    const __nv_bfloat16* Bh = (const __nv_bfloat16*)Bv + (PROJ ? (size_t)blockIdx.z * sB : 0);
    float* Cf = (float*)Cv + (PROJ ? (size_t)blockIdx.z * sC : 0);
    __nv_bfloat16* Ch = (__nv_bfloat16*)Cv + (PROJ ? 0 : (size_t)blockIdx.z * sC);
    if (PROJ && resid) resid += (size_t)blockIdx.z * sR;

    int am[4], ak[4];
#pragma unroll
    for (int i = 0; i < 4; i++) {
        int e = tid + i * 256;
        am[i] = e >> 3; ak[i] = (e & 7) * 4;
    }
    int bk0[4], bn0[4];
#pragma unroll
    for (int i = 0; i < 4; i++) {
        int e = tid + i * 256;
        if (!PROJ) { bk0[i] = e >> 5; bn0[i] = (e & 31) * 4; }
        else       { bn0[i] = e >> 3; bk0[i] = (e & 7) * 4; }
    }

    float acc[4][4][4];
#pragma unroll
    for (int mf = 0; mf < 4; mf++)
#pragma unroll
        for (int nf = 0; nf < 4; nf++)
#pragma unroll
            for (int r = 0; r < 4; r++) acc[mf][nf][r] = 0.f;

    float4 pa[4];
    float4 pbf[4];
    uint2  pbh[4];
#pragma unroll
    for (int i = 0; i < 4; i++)
        pa[i] = *(const float4*)&A[(size_t)(m0 + am[i]) * lda + ak[i]];
#pragma unroll
    for (int i = 0; i < 4; i++) {
        if (!PROJ) pbf[i] = *(const float4*)&Bf[(size_t)bk0[i] * ldb + n0 + bn0[i]];
        else       pbh[i] = *(const uint2*)&Bh[(size_t)(n0 + bn0[i]) * ldb + bk0[i]];
    }

    const uint32_t* As32 = (const uint32_t*)As;
    const uint32_t* Bs32 = (const uint32_t*)Bs;

    for (int k0 = 0; k0 < K; k0 += 32) {
#pragma unroll
        for (int i = 0; i < 4; i++) {
            uint2 t;
            t.x = packb(pa[i].x, pa[i].y);
            t.y = packb(pa[i].z, pa[i].w);
            *(uint2*)&As[am[i]][ak[i]] = t;
        }
#pragma unroll
        for (int i = 0; i < 4; i++) {
            if (!PROJ) {
                Bs[bn0[i] + 0][bk0[i]] = __float2bfloat16_rn(pbf[i].x);
                Bs[bn0[i] + 1][bk0[i]] = __float2bfloat16_rn(pbf[i].y);
                Bs[bn0[i] + 2][bk0[i]] = __float2bfloat16_rn(pbf[i].z);
                Bs[bn0[i] + 3][bk0[i]] = __float2bfloat16_rn(pbf[i].w);
            } else {
                *(uint2*)&Bs[bn0[i]][bk0[i]] = pbh[i];
            }
        }
        __syncthreads();

        if (k0 + 32 < K) {
            int kn = k0 + 32;
#pragma unroll
            for (int i = 0; i < 4; i++)
                pa[i] = *(const float4*)&A[(size_t)(m0 + am[i]) * lda + kn + ak[i]];
#pragma unroll
            for (int i = 0; i < 4; i++) {
                if (!PROJ) pbf[i] = *(const float4*)&Bf[(size_t)(kn + bk0[i]) * ldb + n0 + bn0[i]];
                else       pbh[i] = *(const uint2*)&Bh[(size_t)(n0 + bn0[i]) * ldb + kn + bk0[i]];
            }
        }

#pragma unroll
        for (int kc = 0; kc < 2; kc++) {
            uint32_t af[4][4];
#pragma unroll
            for (int mf = 0; mf < 4; mf++) {
                int mr = wm * 64 + mf * 16 + g;
                af[mf][0] = As32[mr * 20 + kc * 8 + tg];
                af[mf][1] = As32[(mr + 8) * 20 + kc * 8 + tg];
                af[mf][2] = As32[mr * 20 + kc * 8 + tg + 4];
                af[mf][3] = As32[(mr + 8) * 20 + kc * 8 + tg + 4];
            }
#pragma unroll
            for (int nf = 0; nf < 4; nf++) {
                int nc = wn * 32 + nf * 8 + g;
                uint32_t b0 = Bs32[nc * 20 + kc * 8 + tg];
                uint32_t b1 = Bs32[nc * 20 + kc * 8 + tg + 4];
#pragma unroll
                for (int mf = 0; mf < 4; mf++)
                    mma_bf16(acc[mf][nf], af[mf], b0, b1);
            }
        }
        __syncthreads();
    }

#pragma unroll
    for (int mf = 0; mf < 4; mf++) {
        int m = m0 + wm * 64 + mf * 16 + g;
        float bi0 = bias[m], bi1 = bias[m + 8];
#pragma unroll
        for (int nf = 0; nf < 4; nf++) {
            int n = n0 + wn * 32 + nf * 8 + tg * 2;
            float v0 = acc[mf][nf][0] + bi0, v1 = acc[mf][nf][1] + bi0;
            float v2 = acc[mf][nf][2] + bi1, v3 = acc[mf][nf][3] + bi1;
            if (!PROJ) {
                *(uint32_t*)&Ch[(size_t)m * ldc + n] = packb(v0, v1);
                *(uint32_t*)&Ch[(size_t)(m + 8) * ldc + n] = packb(v2, v3);
            } else {
                float2 r0 = *(const float2*)&resid[(size_t)m * ldc + n];
                float2 r1 = *(const float2*)&resid[(size_t)(m + 8) * ldc + n];
                *(float2*)&Cf[(size_t)m * ldc + n] = make_float2(v0 + r0.x, v1 + r0.y);
                *(float2*)&Cf[(size_t)(m + 8) * ldc + n] = make_float2(v2 + r1.x, v3 + r1.y);
            }
        }
    }
}

// ---------------- fused flash attention ---------------------------------------
// 4 warps x 32 q-rows = 128-row q tile, 128 threads. KV tile 64.
// K and V both stored [d][m] in smem (stride 72 bf16); K frags via ldmatrix.trans,
// V frags via ldmatrix. Each B-fragment feeds 2 A-sets (32 FLOP/smem byte).
__global__ void __launch_bounds__(128)
flash_attn(const __nv_bfloat16* __restrict__ qkv, __nv_bfloat16* __restrict__ aoT) {
    __shared__ __nv_bfloat16 Ksm[64][72];  // [d][m]
    __shared__ __nv_bfloat16 Vsm[64][72];  // [d][m]
    const int tid = threadIdx.x;
    const int w = tid >> 5, lane = tid & 31;
    const int g = lane >> 2, tg = lane & 3;

    const int b = blockIdx.z, h = blockIdx.y;
    const size_t CN = (size_t)CCH * NTOK;
    const __nv_bfloat16* qg = qkv + (size_t)b * 3 * CN + (size_t)(h * HD) * NTOK;
    const __nv_bfloat16* kg = qg + CN;
    const __nv_bfloat16* vg = qg + 2 * CN;

    const int nq0 = blockIdx.x * 128 + w * 32;

    // ldmatrix per-lane base addresses
    const uint32_t ksm0 = (uint32_t)__cvta_generic_to_shared(&Ksm[0][0]);
    const uint32_t vsm0 = (uint32_t)__cvta_generic_to_shared(&Vsm[0][0]);
    const int mat = lane >> 3, r = lane & 7;
    // K (trans): row d = (mat&1)*8 + r  (+ kc*16), col m = (mat>>1)*8 (+ p*16)
    const uint32_t kbase = ksm0 + (uint32_t)(((mat & 1) * 8 + r) * 144 + (mat >> 1) * 16);
    // V (no trans): row d = r (+ dt*8), col m = mat*8 (+ mcp*32)
    const uint32_t vbase = vsm0 + (uint32_t)(r * 144 + mat * 16);

    // ---- Q fragments, 2 sets of 16 rows, pre-scaled ----
    uint32_t qa[2][4][4];
#pragma unroll
    for (int s = 0; s < 2; s++)
#pragma unroll
        for (int kc = 0; kc < 4; kc++) {
            int d0 = kc * 16 + 2 * tg;
#pragma unroll
            for (int rr = 0; rr < 2; rr++) {
                int q = nq0 + s * 16 + g + rr * 8;
                float lo0 = __bfloat162float(qg[(size_t)d0 * NTOK + q]) * 0.125f;
                float hi0 = __bfloat162float(qg[(size_t)(d0 + 1) * NTOK + q]) * 0.125f;
                float lo8 = __bfloat162float(qg[(size_t)(d0 + 8) * NTOK + q]) * 0.125f;
                float hi8 = __bfloat162float(qg[(size_t)(d0 + 9) * NTOK + q]) * 0.125f;
                qa[s][kc][rr] = packb(lo0, hi0);
                qa[s][kc][rr + 2] = packb(lo8, hi8);
            }
        }

    float o[2][8][4];
#pragma unroll
    for (int s = 0; s < 2; s++)
#pragma unroll
        for (int i = 0; i < 8; i++)
#pragma unroll
            for (int j = 0; j < 4; j++) o[s][i][j] = 0.f;
    float mrow[2][2] = {{-1e30f, -1e30f}, {-1e30f, -1e30f}};
    float lrow[2][2] = {{0.f, 0.f}, {0.f, 0.f}};

    // K/V tile loader indices + prefetch regs
    int ld_d[8], ld_m[8];
#pragma unroll
    for (int i = 0; i < 8; i++) {
        int e = tid + i * 128;
        ld_d[i] = e >> 4;
        ld_m[i] = (e & 15) * 4;
    }
    uint2 pk[8], pv[8];
#pragma unroll
    for (int i = 0; i < 8; i++) {
        pk[i] = *(const uint2*)&kg[(size_t)ld_d[i] * NTOK + ld_m[i]];
        pv[i] = *(const uint2*)&vg[(size_t)ld_d[i] * NTOK + ld_m[i]];
    }

    for (int kt = 0; kt < NTOK / 64; kt++) {
        __syncthreads();
#pragma unroll
        for (int i = 0; i < 8; i++) {
            *(uint2*)&Ksm[ld_d[i]][ld_m[i]] = pk[i];
            *(uint2*)&Vsm[ld_d[i]][ld_m[i]] = pv[i];
        }
        __syncthreads();
        if (kt + 1 < NTOK / 64) {
            int mt = (kt + 1) * 64;
#pragma unroll
            for (int i = 0; i < 8; i++) {
                pk[i] = *(const uint2*)&kg[(size_t)ld_d[i] * NTOK + mt + ld_m[i]];
                pv[i] = *(const uint2*)&vg[(size_t)ld_d[i] * NTOK + mt + ld_m[i]];
            }
        }

        // ---- S = Q^T K : 32 x 64 per warp, both sets share K frags ----
        float c[2][8][4];
#pragma unroll
        for (int s = 0; s < 2; s++)
#pragma unroll
            for (int nt = 0; nt < 8; nt++)
                c[s][nt][0] = c[s][nt][1] = c[s][nt][2] = c[s][nt][3] = 0.f;

#pragma unroll
        for (int p = 0; p < 4; p++) {       // nt pair = 2p, 2p+1
#pragma unroll
            for (int kc = 0; kc < 4; kc++) {
                uint32_t kb[4];
                ldsm4t(kb, kbase + (uint32_t)(kc * 2304 + p * 32));
                mma_bf16(c[0][2 * p], qa[0][kc], kb[0], kb[1]);
                mma_bf16(c[1][2 * p], qa[1][kc], kb[0], kb[1]);
                mma_bf16(c[0][2 * p + 1], qa[0][kc], kb[2], kb[3]);
                mma_bf16(c[1][2 * p + 1], qa[1][kc], kb[2], kb[3]);
            }
        }

        // ---- online softmax + pack P, per set ----
        uint32_t pa[2][4][4];
#pragma unroll
        for (int s = 0; s < 2; s++) {
            float tm0 = -1e30f, tm1 = -1e30f;
#pragma unroll
            for (int nt = 0; nt < 8; nt++) {
                tm0 = fmaxf(tm0, fmaxf(c[s][nt][0], c[s][nt][1]));
                tm1 = fmaxf(tm1, fmaxf(c[s][nt][2], c[s][nt][3]));
            }
            tm0 = fmaxf(tm0, __shfl_xor_sync(0xffffffffu, tm0, 1));
            tm0 = fmaxf(tm0, __shfl_xor_sync(0xffffffffu, tm0, 2));
            tm1 = fmaxf(tm1, __shfl_xor_sync(0xffffffffu, tm1, 1));
            tm1 = fmaxf(tm1, __shfl_xor_sync(0xffffffffu, tm1, 2));
            float nm0 = fmaxf(mrow[s][0], tm0), nm1 = fmaxf(mrow[s][1], tm1);
            float a0 = ex2f((mrow[s][0] - nm0) * LOG2E);
            float a1 = ex2f((mrow[s][1] - nm1) * LOG2E);
            mrow[s][0] = nm0; mrow[s][1] = nm1;
            float nmL0 = nm0 * LOG2E, nmL1 = nm1 * LOG2E;
            float s0 = 0.f, s1 = 0.f;
#pragma unroll
            for (int nt = 0; nt < 8; nt++) {
                c[s][nt][0] = ex2f(fmaf(c[s][nt][0], LOG2E, -nmL0));
                c[s][nt][1] = ex2f(fmaf(c[s][nt][1], LOG2E, -nmL0));
                c[s][nt][2] = ex2f(fmaf(c[s][nt][2], LOG2E, -nmL1));
                c[s][nt][3] = ex2f(fmaf(c[s][nt][3], LOG2E, -nmL1));
                s0 += c[s][nt][0] + c[s][nt][1];
                s1 += c[s][nt][2] + c[s][nt][3];
            }
            s0 += __shfl_xor_sync(0xffffffffu, s0, 1);
            s0 += __shfl_xor_sync(0xffffffffu, s0, 2);
            s1 += __shfl_xor_sync(0xffffffffu, s1, 1);
            s1 += __shfl_xor_sync(0xffffffffu, s1, 2);
            lrow[s][0] = lrow[s][0] * a0 + s0;
            lrow[s][1] = lrow[s][1] * a1 + s1;
#pragma unroll
            for (int nt = 0; nt < 8; nt++) {
                o[s][nt][0] *= a0; o[s][nt][1] *= a0;
                o[s][nt][2] *= a1; o[s][nt][3] *= a1;
            }
#pragma unroll
            for (int mc = 0; mc < 4; mc++) {
                pa[s][mc][0] = packb(c[s][2 * mc][0], c[s][2 * mc][1]);
                pa[s][mc][1] = packb(c[s][2 * mc][2], c[s][2 * mc][3]);
                pa[s][mc][2] = packb(c[s][2 * mc + 1][0], c[s][2 * mc + 1][1]);
                pa[s][mc][3] = packb(c[s][2 * mc + 1][2], c[s][2 * mc + 1][3]);
            }
        }

        // ---- O += P @ V^T, both sets share V frags ----
#pragma unroll
        for (int dt = 0; dt < 8; dt++) {
#pragma unroll
            for (int mcp = 0; mcp < 2; mcp++) {
                uint32_t vb[4];
                ldsm4(vb, vbase + (uint32_t)(dt * 1152 + mcp * 64));
                mma_bf16(o[0][dt], pa[0][2 * mcp], vb[0], vb[1]);
                mma_bf16(o[1][dt], pa[1][2 * mcp], vb[0], vb[1]);
                mma_bf16(o[0][dt], pa[0][2 * mcp + 1], vb[2], vb[3]);
                mma_bf16(o[1][dt], pa[1][2 * mcp + 1], vb[2], vb[3]);
            }
        }
    }

    // ---- epilogue -> bf16 aoT[n][h*64+d] ----
    __nv_bfloat16* outp = aoT + (size_t)b * CN + (size_t)(h * HD);
#pragma unroll
    for (int s = 0; s < 2; s++) {
        float inv0 = 1.f / lrow[s][0], inv1 = 1.f / lrow[s][1];
        int q0 = nq0 + s * 16;
#pragma unroll
        for (int dt = 0; dt < 8; dt++) {
            *(uint32_t*)&outp[(size_t)(q0 + g) * CCH + dt * 8 + tg * 2] =
                packb(o[s][dt][0] * inv0, o[s][dt][1] * inv0);
            *(uint32_t*)&outp[(size_t)(q0 + g + 8) * CCH + dt * 8 + tg * 2] =
                packb(o[s][dt][2] * inv1, o[s][dt][3] * inv1);
        }
    }
}

// ---------------- launch ------------------------------------------------------
extern "C" void kernel_launch(void* const* d_in, const int* in_sizes, int n_in,
                              void* d_out, int out_size) {
    const float* x      = (const float*)d_in[0];
    const float* norm_w = (const float*)d_in[1];
    const float* norm_b = (const float*)d_in[2];
    const float* qkv_w  = (const float*)d_in[3];
    const float* qkv_b  = (const float*)d_in[4];
    const float* proj_w = (const float*)d_in[5];
    const float* proj_b = (const float*)d_in[6];
    float* out = (float*)d_out;

    float* hn;
    __nv_bfloat16 *qkv, *aoT;
    cudaGetSymbolAddress((void**)&hn,  g_hn);
    cudaGetSymbolAddress((void**)&qkv, g_qkv);
    cudaGetSymbolAddress((void**)&aoT, g_aoT);

    const size_t CN = (size_t)CCH * NTOK;

    // 1) GroupNorm
    gn_stats<<<dim3(8, BATCH * GROUPS), 256>>>(x);
    gn_apply<<<dim3(8, BATCH * GROUPS), 256>>>(x, norm_w, norm_b);

    // 2) QKV GEMM (bf16 tensor): [1536,512] x [512,4096] -> bf16 qkv
    gemm_bf16<false><<<dim3(NTOK / 128, (3 * CCH) / 128, BATCH), 256>>>(
        qkv_w, hn, qkv, CCH, CCH, NTOK, NTOK,
        CN, 3 * CN, qkv_b, nullptr, 0);

    // 3) fused attention (bf16, ldmatrix, 2 A-sets per warp)
    flash_attn<<<dim3(NTOK / 128, NH, BATCH), 128>>>(qkv, aoT);

    // 4) proj (bf16 tensor) + bias + residual -> fp32 out
    gemm_bf16<true><<<dim3(NTOK / 128, CCH / 128, BATCH), 256>>>(
        proj_w, aoT, out, CCH, CCH, CCH, NTOK,
        CN, CN, proj_b, x, CN);
}

// round 7
// speedup vs baseline: 10.6615x; 1.1002x over previous
#include <cuda_runtime.h>
#include <cuda_bf16.h>
#include <math.h>
#include <stdint.h>

#define BATCH 2
#define CCH 512
#define NH 8
#define HD 64
#define GROUPS 32
#define NTOK 4096
#define EPS 1e-5f
#define LOG2E 1.44269504f

// ---------------- scratch (static device globals; no allocation) -------------
__device__ __nv_bfloat16 g_hn[(size_t)BATCH * CCH * NTOK];          // 8 MB
__device__ __nv_bfloat16 g_qkv[(size_t)BATCH * 3 * CCH * NTOK];     // 25 MB
__device__ __nv_bfloat16 g_aoT[(size_t)BATCH * NTOK * CCH];         // 8 MB [b][n][c]
__device__ float g_gnpart[BATCH * GROUPS][8][2];

// ---------------- helpers -----------------------------------------------------
__device__ __forceinline__ uint32_t packb(float lo, float hi) {
    __nv_bfloat162 t = __floats2bfloat162_rn(lo, hi);
    return *(uint32_t*)&t;
}
__device__ __forceinline__ float ex2f(float x) {
    float y;
    asm("ex2.approx.f32 %0, %1;" : "=f"(y) : "f"(x));
    return y;
}
// packed bf16x2 exp2 of (lo, hi)
__device__ __forceinline__ uint32_t ex2b(float lo, float hi) {
    __nv_bfloat162 t = __floats2bfloat162_rn(lo, hi);
    uint32_t u = *(uint32_t*)&t, y;
    asm("ex2.approx.ftz.bf16x2 %0, %1;" : "=r"(y) : "r"(u));
    return y;
}
__device__ __forceinline__ void mma_bf16(float c[4], const uint32_t a[4],
                                         uint32_t b0, uint32_t b1) {
    asm volatile(
        "mma.sync.aligned.m16n8k16.row.col.f32.bf16.bf16.f32 "
        "{%0,%1,%2,%3}, {%4,%5,%6,%7}, {%8,%9}, {%0,%1,%2,%3};\n"
        : "+f"(c[0]), "+f"(c[1]), "+f"(c[2]), "+f"(c[3])
        : "r"(a[0]), "r"(a[1]), "r"(a[2]), "r"(a[3]), "r"(b0), "r"(b1));
}
__device__ __forceinline__ void ldsm4t(uint32_t r[4], uint32_t addr) {
    asm volatile(
        "ldmatrix.sync.aligned.m8n8.x4.trans.shared.b16 {%0,%1,%2,%3}, [%4];"
        : "=r"(r[0]), "=r"(r[1]), "=r"(r[2]), "=r"(r[3]) : "r"(addr));
}
__device__ __forceinline__ void ldsm4(uint32_t r[4], uint32_t addr) {
    asm volatile(
        "ldmatrix.sync.aligned.m8n8.x4.shared.b16 {%0,%1,%2,%3}, [%4];"
        : "=r"(r[0]), "=r"(r[1]), "=r"(r[2]), "=r"(r[3]) : "r"(addr));
}
#define CP_ASYNC16(dst, src) \
    asm volatile("cp.async.cg.shared.global [%0], [%1], 16;" :: "r"(dst), "l"(src))
#define CP_COMMIT() asm volatile("cp.async.commit_group;")
#define CP_WAIT_ALL() asm volatile("cp.async.wait_group 0;")

// ---------------- GroupNorm: stats + apply ------------------------------------
__global__ void gn_stats(const float* __restrict__ x) {
    int bg = blockIdx.y, sl = blockIdx.x, tid = threadIdx.x;
    const float4* xp = (const float4*)x + (size_t)bg * 16384 + sl * 2048;
    float s = 0.f, s2 = 0.f;
    for (int i = tid; i < 2048; i += 256) {
        float4 v = xp[i];
        s += v.x + v.y + v.z + v.w;
        s2 += v.x * v.x + v.y * v.y + v.z * v.z + v.w * v.w;
    }
    __shared__ float sh[256], sh2[256];
    sh[tid] = s; sh2[tid] = s2;
    __syncthreads();
    for (int o = 128; o > 0; o >>= 1) {
        if (tid < o) { sh[tid] += sh[tid + o]; sh2[tid] += sh2[tid + o]; }
        __syncthreads();
    }
    if (tid == 0) {
        g_gnpart[bg][sl][0] = sh[0];
        g_gnpart[bg][sl][1] = sh2[0];
    }
}

__global__ void gn_apply(const float* __restrict__ x,
                         const float* __restrict__ w,
                         const float* __restrict__ b) {
    int bg = blockIdx.y, sl = blockIdx.x, tid = threadIdx.x;
    float S = 0.f, S2 = 0.f;
#pragma unroll
    for (int i = 0; i < 8; i++) {
        S += g_gnpart[bg][i][0];
        S2 += g_gnpart[bg][i][1];
    }
    float mean = S / 65536.f;
    float var  = S2 / 65536.f - mean * mean;
    float inv  = rsqrtf(var + EPS);
    int g = bg % GROUPS;
    const float4* xp = (const float4*)x + (size_t)bg * 16384 + sl * 2048;
    uint2* hp = (uint2*)(g_hn + (size_t)bg * 65536 + sl * 8192);
    for (int i = tid; i < 2048; i += 256) {
        int ch = g * 16 + sl * 2 + (i >> 10);
        float sc = inv * w[ch];
        float off = b[ch] - mean * sc;
        float4 v = xp[i];
        uint2 o;
        o.x = packb(v.x * sc + off, v.y * sc + off);
        o.y = packb(v.z * sc + off, v.w * sc + off);
        hp[i] = o;
    }
}

// ---------------- bf16 tensor GEMM: 128x128, BK=32 ----------------------------
// MODE 0 (QKV): B bf16 [k][n] (ldb along n), C bf16.
// MODE 1 (PROJ): B bf16 [n][k] (ldb along k), C fp32 + resid.
template <int MODE>
__global__ void __launch_bounds__(256, 2)
gemm_bf16(const float* __restrict__ A, const __nv_bfloat16* __restrict__ B,
          void* __restrict__ Cv, int K, int lda, int ldb, int ldc,
          size_t sB, size_t sC,
          const float* __restrict__ bias,
          const float* __restrict__ resid, size_t sR) {
    __shared__ __nv_bfloat16 As[128][40];   // [m][k]
    __shared__ __nv_bfloat16 Bs[128][40];   // [n][k]

    const int tid = threadIdx.x;
    const int w = tid >> 5, lane = tid & 31;
    const int g = lane >> 2, tg = lane & 3;
    const int wm = w >> 2, wn = w & 3;
    const int m0 = blockIdx.y * 128;
    const int n0 = blockIdx.x * 128;

    B += (size_t)blockIdx.z * sB;
    float* Cf = (float*)Cv + (MODE == 1 ? (size_t)blockIdx.z * sC : 0);
    __nv_bfloat16* Ch = (__nv_bfloat16*)Cv + (MODE == 0 ? (size_t)blockIdx.z * sC : 0);
    if (MODE == 1 && resid) resid += (size_t)blockIdx.z * sR;

    int am[4], ak[4];
#pragma unroll
    for (int i = 0; i < 4; i++) {
        int e = tid + i * 256;
        am[i] = e >> 3; ak[i] = (e & 7) * 4;
    }
    int bk0[4], bn0[4];
#pragma unroll
    for (int i = 0; i < 4; i++) {
        int e = tid + i * 256;
        if (MODE == 0) { bk0[i] = e >> 5; bn0[i] = (e & 31) * 4; }  // [k][n]
        else           { bn0[i] = e >> 3; bk0[i] = (e & 7) * 4; }   // [n][k]
    }

    float acc[4][4][4];
#pragma unroll
    for (int mf = 0; mf < 4; mf++)
#pragma unroll
        for (int nf = 0; nf < 4; nf++)
#pragma unroll
            for (int r = 0; r < 4; r++) acc[mf][nf][r] = 0.f;

    float4 pa[4];
    uint2  pb[4];
#pragma unroll
    for (int i = 0; i < 4; i++)
        pa[i] = *(const float4*)&A[(size_t)(m0 + am[i]) * lda + ak[i]];
#pragma unroll
    for (int i = 0; i < 4; i++) {
        if (MODE == 0) pb[i] = *(const uint2*)&B[(size_t)bk0[i] * ldb + n0 + bn0[i]];
        else           pb[i] = *(const uint2*)&B[(size_t)(n0 + bn0[i]) * ldb + bk0[i]];
    }

    const uint32_t* As32 = (const uint32_t*)As;
    const uint32_t* Bs32 = (const uint32_t*)Bs;

    for (int k0 = 0; k0 < K; k0 += 32) {
#pragma unroll
        for (int i = 0; i < 4; i++) {
            uint2 t;
            t.x = packb(pa[i].x, pa[i].y);
            t.y = packb(pa[i].z, pa[i].w);
            *(uint2*)&As[am[i]][ak[i]] = t;
        }
#pragma unroll
        for (int i = 0; i < 4; i++) {
            if (MODE == 0) {
                __nv_bfloat162 p01 = *(__nv_bfloat162*)&pb[i].x;
                __nv_bfloat162 p23 = *(__nv_bfloat162*)&pb[i].y;
                Bs[bn0[i] + 0][bk0[i]] = p01.x;
                Bs[bn0[i] + 1][bk0[i]] = p01.y;
                Bs[bn0[i] + 2][bk0[i]] = p23.x;
                Bs[bn0[i] + 3][bk0[i]] = p23.y;
            } else {
                *(uint2*)&Bs[bn0[i]][bk0[i]] = pb[i];
            }
        }
        __syncthreads();

        if (k0 + 32 < K) {
            int kn = k0 + 32;
#pragma unroll
            for (int i = 0; i < 4; i++)
                pa[i] = *(const float4*)&A[(size_t)(m0 + am[i]) * lda + kn + ak[i]];
#pragma unroll
            for (int i = 0; i < 4; i++) {
                if (MODE == 0) pb[i] = *(const uint2*)&B[(size_t)(kn + bk0[i]) * ldb + n0 + bn0[i]];
                else           pb[i] = *(const uint2*)&B[(size_t)(n0 + bn0[i]) * ldb + kn + bk0[i]];
            }
        }

#pragma unroll
        for (int kc = 0; kc < 2; kc++) {
            uint32_t af[4][4];
#pragma unroll
            for (int mf = 0; mf < 4; mf++) {
                int mr = wm * 64 + mf * 16 + g;
                af[mf][0] = As32[mr * 20 + kc * 8 + tg];
                af[mf][1] = As32[(mr + 8) * 20 + kc * 8 + tg];
                af[mf][2] = As32[mr * 20 + kc * 8 + tg + 4];
                af[mf][3] = As32[(mr + 8) * 20 + kc * 8 + tg + 4];
            }
#pragma unroll
            for (int nf = 0; nf < 4; nf++) {
                int nc = wn * 32 + nf * 8 + g;
                uint32_t b0 = Bs32[nc * 20 + kc * 8 + tg];
                uint32_t b1 = Bs32[nc * 20 + kc * 8 + tg + 4];
#pragma unroll
                for (int mf = 0; mf < 4; mf++)
                    mma_bf16(acc[mf][nf], af[mf], b0, b1);
            }
        }
        __syncthreads();
    }

#pragma unroll
    for (int mf = 0; mf < 4; mf++) {
        int m = m0 + wm * 64 + mf * 16 + g;
        float bi0 = bias[m], bi1 = bias[m + 8];
#pragma unroll
        for (int nf = 0; nf < 4; nf++) {
            int n = n0 + wn * 32 + nf * 8 + tg * 2;
            float v0 = acc[mf][nf][0] + bi0, v1 = acc[mf][nf][1] + bi0;
            float v2 = acc[mf][nf][2] + bi1, v3 = acc[mf][nf][3] + bi1;
            if (MODE == 0) {
                *(uint32_t*)&Ch[(size_t)m * ldc + n] = packb(v0, v1);
                *(uint32_t*)&Ch[(size_t)(m + 8) * ldc + n] = packb(v2, v3);
            } else {
                float2 r0 = *(const float2*)&resid[(size_t)m * ldc + n];
                float2 r1 = *(const float2*)&resid[(size_t)(m + 8) * ldc + n];
                *(float2*)&Cf[(size_t)m * ldc + n] = make_float2(v0 + r0.x, v1 + r0.y);
                *(float2*)&Cf[(size_t)(m + 8) * ldc + n] = make_float2(v2 + r1.x, v3 + r1.y);
            }
        }
    }
}

// ---------------- fused flash attention ---------------------------------------
// 4 warps x 32 q-rows = 128-row q tile, 128 threads, KV tile 64, double-buffered
// cp.async. S in log2 units (log2e folded into Q). P = ex2.bf16x2 directly into
// A-fragments. Row-sum l via ones-row appended to V (tensor-core reduction).
#define KSTG 9216    // 64*72*2 bytes per K stage
#define VSTG 10368   // 72*72*2 bytes per V stage

__global__ void __launch_bounds__(128)
flash_attn(const __nv_bfloat16* __restrict__ qkv, __nv_bfloat16* __restrict__ aoT) {
    __shared__ __nv_bfloat16 Ksm[2][64][72];  // [d][m]
    __shared__ __nv_bfloat16 Vsm[2][72][72];  // [d][m], rows 64..71: ones block
    const int tid = threadIdx.x;
    const int w = tid >> 5, lane = tid & 31;
    const int g = lane >> 2, tg = lane & 3;

    const int b = blockIdx.z, h = blockIdx.y;
    const size_t CN = (size_t)CCH * NTOK;
    const __nv_bfloat16* qg = qkv + (size_t)b * 3 * CN + (size_t)(h * HD) * NTOK;
    const __nv_bfloat16* kg = qg + CN;
    const __nv_bfloat16* vg = qg + 2 * CN;

    const int nq0 = blockIdx.x * 128 + w * 32;

    // ones/zeros rows (both stages), written once; never touched by tile loads
    for (int i = tid; i < 2 * 8 * 72; i += 128) {
        int st = i / 576, rr = (i / 72) % 8, cc = i % 72;
        Vsm[st][64 + rr][cc] = __float2bfloat16(rr == 0 ? 1.0f : 0.0f);
    }

    // cp.async loader: 16B per op, 4 K + 4 V per thread per tile
    int ld_d[4], ld_m[4];
    uint32_t kdst[4], vdst[4];
#pragma unroll
    for (int i = 0; i < 4; i++) {
        int e = tid + i * 128;
        ld_d[i] = e >> 3; ld_m[i] = (e & 7) * 8;
        kdst[i] = (uint32_t)__cvta_generic_to_shared(&Ksm[0][ld_d[i]][ld_m[i]]);
        vdst[i] = (uint32_t)__cvta_generic_to_shared(&Vsm[0][ld_d[i]][ld_m[i]]);
    }
    // prologue: tile 0 -> stage 0
#pragma unroll
    for (int i = 0; i < 4; i++) {
        CP_ASYNC16(kdst[i], kg + (size_t)ld_d[i] * NTOK + ld_m[i]);
        CP_ASYNC16(vdst[i], vg + (size_t)ld_d[i] * NTOK + ld_m[i]);
    }
    CP_COMMIT();

    // Q fragments (scale * log2e folded in)
    const float qs = 0.125f * LOG2E;
    uint32_t qa[2][4][4];
#pragma unroll
    for (int s = 0; s < 2; s++)
#pragma unroll
        for (int kc = 0; kc < 4; kc++) {
            int d0 = kc * 16 + 2 * tg;
#pragma unroll
            for (int rr = 0; rr < 2; rr++) {
                int q = nq0 + s * 16 + g + rr * 8;
                float lo0 = __bfloat162float(qg[(size_t)d0 * NTOK + q]) * qs;
                float hi0 = __bfloat162float(qg[(size_t)(d0 + 1) * NTOK + q]) * qs;
                float lo8 = __bfloat162float(qg[(size_t)(d0 + 8) * NTOK + q]) * qs;
                float hi8 = __bfloat162float(qg[(size_t)(d0 + 9) * NTOK + q]) * qs;
                qa[s][kc][rr] = packb(lo0, hi0);
                qa[s][kc][rr + 2] = packb(lo8, hi8);
            }
        }

    float o[2][8][4];
    float o_l[2][4];
#pragma unroll
    for (int s = 0; s < 2; s++) {
#pragma unroll
        for (int i = 0; i < 8; i++)
#pragma unroll
            for (int j = 0; j < 4; j++) o[s][i][j] = 0.f;
#pragma unroll
        for (int j = 0; j < 4; j++) o_l[s][j] = 0.f;
    }
    float mrow[2][2] = {{-1e30f, -1e30f}, {-1e30f, -1e30f}};

    const uint32_t ksm0 = (uint32_t)__cvta_generic_to_shared(&Ksm[0][0][0]);
    const uint32_t vsm0 = (uint32_t)__cvta_generic_to_shared(&Vsm[0][0][0]);
    const int mat = lane >> 3, r = lane & 7;
    const uint32_t kfrag = ksm0 + (uint32_t)(((mat & 1) * 8 + r) * 144 + (mat >> 1) * 16);
    const uint32_t vfrag = vsm0 + (uint32_t)(r * 144 + mat * 16);

    for (int kt = 0; kt < NTOK / 64; kt++) {
        const int st = kt & 1;
        CP_WAIT_ALL();
        __syncthreads();
        if (kt + 1 < NTOK / 64) {
            int mt = (kt + 1) * 64, s2 = st ^ 1;
#pragma unroll
            for (int i = 0; i < 4; i++) {
                CP_ASYNC16(kdst[i] + s2 * KSTG, kg + (size_t)ld_d[i] * NTOK + mt + ld_m[i]);
                CP_ASYNC16(vdst[i] + s2 * VSTG, vg + (size_t)ld_d[i] * NTOK + mt + ld_m[i]);
            }
            CP_COMMIT();
        }
        const uint32_t kst = kfrag + st * KSTG;
        const uint32_t vst = vfrag + st * VSTG;

        // ---- S = Q^T K (log2 units) ----
        float c[2][8][4];
#pragma unroll
        for (int s = 0; s < 2; s++)
#pragma unroll
            for (int nt = 0; nt < 8; nt++)
                c[s][nt][0] = c[s][nt][1] = c[s][nt][2] = c[s][nt][3] = 0.f;
#pragma unroll
        for (int p = 0; p < 4; p++)
#pragma unroll
            for (int kc = 0; kc < 4; kc++) {
                uint32_t kb[4];
                ldsm4t(kb, kst + (uint32_t)(kc * 2304 + p * 32));
                mma_bf16(c[0][2 * p], qa[0][kc], kb[0], kb[1]);
                mma_bf16(c[1][2 * p], qa[1][kc], kb[0], kb[1]);
                mma_bf16(c[0][2 * p + 1], qa[0][kc], kb[2], kb[3]);
                mma_bf16(c[1][2 * p + 1], qa[1][kc], kb[2], kb[3]);
            }

        // ---- online softmax: max, conditional rescale, packed bf16 exp2 ----
        uint32_t pa[2][4][4];
#pragma unroll
        for (int s = 0; s < 2; s++) {
            float tm0 = -1e30f, tm1 = -1e30f;
#pragma unroll
            for (int nt = 0; nt < 8; nt++) {
                tm0 = fmaxf(tm0, fmaxf(c[s][nt][0], c[s][nt][1]));
                tm1 = fmaxf(tm1, fmaxf(c[s][nt][2], c[s][nt][3]));
            }
            tm0 = fmaxf(tm0, __shfl_xor_sync(0xffffffffu, tm0, 1));
            tm0 = fmaxf(tm0, __shfl_xor_sync(0xffffffffu, tm0, 2));
            tm1 = fmaxf(tm1, __shfl_xor_sync(0xffffffffu, tm1, 1));
            tm1 = fmaxf(tm1, __shfl_xor_sync(0xffffffffu, tm1, 2));
            float nm0 = fmaxf(mrow[s][0], tm0), nm1 = fmaxf(mrow[s][1], tm1);
            if (nm0 != mrow[s][0] || nm1 != mrow[s][1]) {
                float a0 = ex2f(mrow[s][0] - nm0), a1 = ex2f(mrow[s][1] - nm1);
                mrow[s][0] = nm0; mrow[s][1] = nm1;
#pragma unroll
                for (int nt = 0; nt < 8; nt++) {
                    o[s][nt][0] *= a0; o[s][nt][1] *= a0;
                    o[s][nt][2] *= a1; o[s][nt][3] *= a1;
                }
                o_l[s][0] *= a0; o_l[s][1] *= a0;
                o_l[s][2] *= a1; o_l[s][3] *= a1;
            }
            uint32_t pe0[8], pe1[8];
#pragma unroll
            for (int nt = 0; nt < 8; nt++) {
                pe0[nt] = ex2b(c[s][nt][0] - nm0, c[s][nt][1] - nm0);
                pe1[nt] = ex2b(c[s][nt][2] - nm1, c[s][nt][3] - nm1);
            }
#pragma unroll
            for (int mc = 0; mc < 4; mc++) {
                pa[s][mc][0] = pe0[2 * mc];
                pa[s][mc][1] = pe1[2 * mc];
                pa[s][mc][2] = pe0[2 * mc + 1];
                pa[s][mc][3] = pe1[2 * mc + 1];
            }
        }

        // ---- l += P @ ones (rows 64..71 of V, ones at row 64 => col 0) ----
#pragma unroll
        for (int mcp = 0; mcp < 2; mcp++) {
            uint32_t lb[4];
            ldsm4(lb, vst + (uint32_t)(8 * 1152 + mcp * 64));
            mma_bf16(o_l[0], pa[0][2 * mcp], lb[0], lb[1]);
            mma_bf16(o_l[1], pa[1][2 * mcp], lb[0], lb[1]);
            mma_bf16(o_l[0], pa[0][2 * mcp + 1], lb[2], lb[3]);
            mma_bf16(o_l[1], pa[1][2 * mcp + 1], lb[2], lb[3]);
        }

        // ---- O += P @ V^T ----
#pragma unroll
        for (int dt = 0; dt < 8; dt++)
#pragma unroll
            for (int mcp = 0; mcp < 2; mcp++) {
                uint32_t vb[4];
                ldsm4(vb, vst + (uint32_t)(dt * 1152 + mcp * 64));
                mma_bf16(o[0][dt], pa[0][2 * mcp], vb[0], vb[1]);
                mma_bf16(o[1][dt], pa[1][2 * mcp], vb[0], vb[1]);
                mma_bf16(o[0][dt], pa[0][2 * mcp + 1], vb[2], vb[3]);
                mma_bf16(o[1][dt], pa[1][2 * mcp + 1], vb[2], vb[3]);
            }
    }

    // ---- epilogue: l broadcast from tg==0 lanes, write bf16 aoT ----
    __nv_bfloat16* outp = aoT + (size_t)b * CN + (size_t)(h * HD);
#pragma unroll
    for (int s = 0; s < 2; s++) {
        float l0 = __shfl_sync(0xffffffffu, o_l[s][0], lane & 28);
        float l1 = __shfl_sync(0xffffffffu, o_l[s][2], lane & 28);
        float inv0 = 1.f / l0, inv1 = 1.f / l1;
        int q0 = nq0 + s * 16;
#pragma unroll
        for (int dt = 0; dt < 8; dt++) {
            *(uint32_t*)&outp[(size_t)(q0 + g) * CCH + dt * 8 + tg * 2] =
                packb(o[s][dt][0] * inv0, o[s][dt][1] * inv0);
            *(uint32_t*)&outp[(size_t)(q0 + g + 8) * CCH + dt * 8 + tg * 2] =
                packb(o[s][dt][2] * inv1, o[s][dt][3] * inv1);
        }
    }
}

// ---------------- launch ------------------------------------------------------
extern "C" void kernel_launch(void* const* d_in, const int* in_sizes, int n_in,
                              void* d_out, int out_size) {
    const float* x      = (const float*)d_in[0];
    const float* norm_w = (const float*)d_in[1];
    const float* norm_b = (const float*)d_in[2];
    const float* qkv_w  = (const float*)d_in[3];
    const float* qkv_b  = (const float*)d_in[4];
    const float* proj_w = (const float*)d_in[5];
    const float* proj_b = (const float*)d_in[6];
    float* out = (float*)d_out;

    __nv_bfloat16 *hn, *qkv, *aoT;
    cudaGetSymbolAddress((void**)&hn,  g_hn);
    cudaGetSymbolAddress((void**)&qkv, g_qkv);
    cudaGetSymbolAddress((void**)&aoT, g_aoT);

    const size_t CN = (size_t)CCH * NTOK;

    // 1) GroupNorm (writes bf16 hn)
    gn_stats<<<dim3(8, BATCH * GROUPS), 256>>>(x);
    gn_apply<<<dim3(8, BATCH * GROUPS), 256>>>(x, norm_w, norm_b);

    // 2) QKV GEMM (bf16 tensor): [1536,512] x [512,4096] -> bf16 qkv
    gemm_bf16<0><<<dim3(NTOK / 128, (3 * CCH) / 128, BATCH), 256>>>(
        qkv_w, hn, qkv, CCH, CCH, NTOK, NTOK,
        CN, 3 * CN, qkv_b, nullptr, 0);

    // 3) fused attention
    flash_attn<<<dim3(NTOK / 128, NH, BATCH), 128>>>(qkv, aoT);

    // 4) proj (bf16 tensor) + bias + residual -> fp32 out
    gemm_bf16<1><<<dim3(NTOK / 128, CCH / 128, BATCH), 256>>>(
        proj_w, aoT, out, CCH, CCH, CCH, NTOK,
        CN, CN, proj_b, x, CN);
}

// round 8
// speedup vs baseline: 14.7989x; 1.3881x over previous
#include <cuda_runtime.h>
#include <cuda_bf16.h>
#include <math.h>
#include <stdint.h>

#define BATCH 2
#define CCH 512
#define NH 8
#define HD 64
#define GROUPS 32
#define NTOK 4096
#define EPS 1e-5f
#define LOG2E 1.44269504f

// ---------------- scratch (static device globals; no allocation) -------------
__device__ __nv_bfloat16 g_hn[(size_t)BATCH * CCH * NTOK];          // 8 MB
__device__ __nv_bfloat16 g_qkv[(size_t)BATCH * 3 * CCH * NTOK];     // 25 MB
__device__ __nv_bfloat16 g_aoT[(size_t)BATCH * NTOK * CCH];         // 8 MB [b][n][c]
__device__ __nv_bfloat16 g_qkvwb[3 * CCH * CCH];                    // 1.5 MB
__device__ __nv_bfloat16 g_projwb[CCH * CCH];                       // 0.5 MB
__device__ float g_gnpart[BATCH * GROUPS][8][2];

// ---------------- helpers -----------------------------------------------------
__device__ __forceinline__ uint32_t packb(float lo, float hi) {
    __nv_bfloat162 t = __floats2bfloat162_rn(lo, hi);
    return *(uint32_t*)&t;
}
__device__ __forceinline__ float ex2f(float x) {
    float y;
    asm("ex2.approx.f32 %0, %1;" : "=f"(y) : "f"(x));
    return y;
}
__device__ __forceinline__ uint32_t ex2b(float lo, float hi) {
    __nv_bfloat162 t = __floats2bfloat162_rn(lo, hi);
    uint32_t u = *(uint32_t*)&t, y;
    asm("ex2.approx.ftz.bf16x2 %0, %1;" : "=r"(y) : "r"(u));
    return y;
}
__device__ __forceinline__ void mma_bf16(float c[4], const uint32_t a[4],
                                         uint32_t b0, uint32_t b1) {
    asm volatile(
        "mma.sync.aligned.m16n8k16.row.col.f32.bf16.bf16.f32 "
        "{%0,%1,%2,%3}, {%4,%5,%6,%7}, {%8,%9}, {%0,%1,%2,%3};\n"
        : "+f"(c[0]), "+f"(c[1]), "+f"(c[2]), "+f"(c[3])
        : "r"(a[0]), "r"(a[1]), "r"(a[2]), "r"(a[3]), "r"(b0), "r"(b1));
}
__device__ __forceinline__ void ldsm4t(uint32_t r[4], uint32_t addr) {
    asm volatile(
        "ldmatrix.sync.aligned.m8n8.x4.trans.shared.b16 {%0,%1,%2,%3}, [%4];"
        : "=r"(r[0]), "=r"(r[1]), "=r"(r[2]), "=r"(r[3]) : "r"(addr));
}
__device__ __forceinline__ void ldsm4(uint32_t r[4], uint32_t addr) {
    asm volatile(
        "ldmatrix.sync.aligned.m8n8.x4.shared.b16 {%0,%1,%2,%3}, [%4];"
        : "=r"(r[0]), "=r"(r[1]), "=r"(r[2]), "=r"(r[3]) : "r"(addr));
}
#define CP_ASYNC16(dst, src) \
    asm volatile("cp.async.cg.shared.global [%0], [%1], 16;" :: "r"(dst), "l"(src))
#define CP_COMMIT() asm volatile("cp.async.commit_group;")
#define CP_WAIT_ALL() asm volatile("cp.async.wait_group 0;")

// ---------------- weight conversion fp32 -> bf16 ------------------------------
__global__ void cvt_w(const float* __restrict__ qkv_w, const float* __restrict__ proj_w) {
    const int NQ = 3 * CCH * CCH / 4;   // float4 count qkv
    int i = blockIdx.x * 256 + threadIdx.x;
    if (i < NQ) {
        float4 v = ((const float4*)qkv_w)[i];
        uint2 o; o.x = packb(v.x, v.y); o.y = packb(v.z, v.w);
        ((uint2*)g_qkvwb)[i] = o;
    } else {
        int j = i - NQ;
        float4 v = ((const float4*)proj_w)[j];
        uint2 o; o.x = packb(v.x, v.y); o.y = packb(v.z, v.w);
        ((uint2*)g_projwb)[j] = o;
    }
}

// ---------------- GroupNorm: stats + apply ------------------------------------
__global__ void gn_stats(const float* __restrict__ x) {
    int bg = blockIdx.y, sl = blockIdx.x, tid = threadIdx.x;
    const float4* xp = (const float4*)x + (size_t)bg * 16384 + sl * 2048;
    float s = 0.f, s2 = 0.f;
    for (int i = tid; i < 2048; i += 256) {
        float4 v = xp[i];
        s += v.x + v.y + v.z + v.w;
        s2 += v.x * v.x + v.y * v.y + v.z * v.z + v.w * v.w;
    }
    __shared__ float sh[256], sh2[256];
    sh[tid] = s; sh2[tid] = s2;
    __syncthreads();
    for (int o = 128; o > 0; o >>= 1) {
        if (tid < o) { sh[tid] += sh[tid + o]; sh2[tid] += sh2[tid + o]; }
        __syncthreads();
    }
    if (tid == 0) {
        g_gnpart[bg][sl][0] = sh[0];
        g_gnpart[bg][sl][1] = sh2[0];
    }
}

__global__ void gn_apply(const float* __restrict__ x,
                         const float* __restrict__ w,
                         const float* __restrict__ b) {
    int bg = blockIdx.y, sl = blockIdx.x, tid = threadIdx.x;
    float S = 0.f, S2 = 0.f;
#pragma unroll
    for (int i = 0; i < 8; i++) {
        S += g_gnpart[bg][i][0];
        S2 += g_gnpart[bg][i][1];
    }
    float mean = S / 65536.f;
    float var  = S2 / 65536.f - mean * mean;
    float inv  = rsqrtf(var + EPS);
    int g = bg % GROUPS;
    const float4* xp = (const float4*)x + (size_t)bg * 16384 + sl * 2048;
    uint2* hp = (uint2*)(g_hn + (size_t)bg * 65536 + sl * 8192);
    for (int i = tid; i < 2048; i += 256) {
        int ch = g * 16 + sl * 2 + (i >> 10);
        float sc = inv * w[ch];
        float off = b[ch] - mean * sc;
        float4 v = xp[i];
        uint2 o;
        o.x = packb(v.x * sc + off, v.y * sc + off);
        o.y = packb(v.z * sc + off, v.w * sc + off);
        hp[i] = o;
    }
}

// ---------------- bf16 GEMM v2: ldmatrix frags, double-buffered ---------------
// C[m,n] = sum_k A[m,k]*B[..] + bias[m] (+resid)
// A bf16 [m][k] row-major (weights). K=512 fixed (16 iters of 32).
// MODE 0 (QKV): B bf16 [k][n] (ldb=n-stride), C bf16.
// MODE 1 (PROJ): B bf16 [n][k] (ldb=k-stride), C fp32 + resid.
#define ASTG 10240   // 128*40*2
#define BSTG0 8704   // 32*136*2
#define BSTG1 10240  // 128*40*2
template <int MODE>
__global__ void __launch_bounds__(256, 2)
gemm2(const __nv_bfloat16* __restrict__ A, const __nv_bfloat16* __restrict__ B,
      void* __restrict__ Cv, int lda, int ldb, int ldc,
      size_t sB, size_t sC,
      const float* __restrict__ bias,
      const float* __restrict__ resid, size_t sR) {
    constexpr int BSZ = (MODE == 0) ? 32 * 136 : 128 * 40;
    __shared__ __nv_bfloat16 As[2][128][40];
    __shared__ __nv_bfloat16 Bs[2][BSZ];

    const int tid = threadIdx.x;
    const int w = tid >> 5, lane = tid & 31;
    const int g = lane >> 2, tg = lane & 3;
    const int wm = w >> 2, wn = w & 3;
    const int m0 = blockIdx.y * 128;
    const int n0 = blockIdx.x * 128;

    B += (size_t)blockIdx.z * sB;
    float* Cf = (float*)Cv + (MODE == 1 ? (size_t)blockIdx.z * sC : 0);
    __nv_bfloat16* Ch = (__nv_bfloat16*)Cv + (MODE == 0 ? (size_t)blockIdx.z * sC : 0);
    if (MODE == 1 && resid) resid += (size_t)blockIdx.z * sR;

    // loader indices (2 uint4 each for A and B)
    int ar[2], ac[2], br[2], bc[2];
#pragma unroll
    for (int i = 0; i < 2; i++) {
        int e = tid + i * 256;
        ar[i] = e >> 2; ac[i] = (e & 3) * 8;
        if (MODE == 0) { br[i] = e >> 4; bc[i] = (e & 15) * 8; }  // [k][n]
        else           { br[i] = e >> 2; bc[i] = (e & 3) * 8; }   // [n][k]
    }

    // fragment base addresses
    const uint32_t asm0 = (uint32_t)__cvta_generic_to_shared(&As[0][0][0]);
    const uint32_t bsm0 = (uint32_t)__cvta_generic_to_shared(&Bs[0][0]);
    const uint32_t afrag = asm0 + (uint32_t)((lane & 15) * 80 + (lane >> 4) * 16);
    uint32_t bfrag;
    if (MODE == 0)
        bfrag = bsm0 + (uint32_t)((((lane >> 3 & 1) * 8) + (lane & 7)) * 272 + (lane >> 4) * 16);
    else
        bfrag = bsm0 + (uint32_t)((lane & 7) * 80 + (lane >> 3) * 16);

    float acc[4][4][4];
#pragma unroll
    for (int mf = 0; mf < 4; mf++)
#pragma unroll
        for (int nf = 0; nf < 4; nf++)
#pragma unroll
            for (int r = 0; r < 4; r++) acc[mf][nf][r] = 0.f;

    uint4 pa[2], pb[2];
    // prologue: tile 0
#pragma unroll
    for (int i = 0; i < 2; i++) {
        pa[i] = *(const uint4*)&A[(size_t)(m0 + ar[i]) * lda + ac[i]];
        if (MODE == 0) pb[i] = *(const uint4*)&B[(size_t)br[i] * ldb + n0 + bc[i]];
        else           pb[i] = *(const uint4*)&B[(size_t)(n0 + br[i]) * ldb + bc[i]];
    }
#pragma unroll
    for (int i = 0; i < 2; i++) {
        *(uint4*)&As[0][ar[i]][ac[i]] = pa[i];
        if (MODE == 0) *(uint4*)&Bs[0][br[i] * 136 + bc[i]] = pb[i];
        else           *(uint4*)&Bs[0][br[i] * 40 + bc[i]] = pb[i];
    }
    __syncthreads();

    for (int it = 0; it < 16; it++) {
        const int buf = it & 1;
        if (it + 1 < 16) {
            int kk = (it + 1) * 32;
#pragma unroll
            for (int i = 0; i < 2; i++) {
                pa[i] = *(const uint4*)&A[(size_t)(m0 + ar[i]) * lda + kk + ac[i]];
                if (MODE == 0) pb[i] = *(const uint4*)&B[(size_t)(kk + br[i]) * ldb + n0 + bc[i]];
                else           pb[i] = *(const uint4*)&B[(size_t)(n0 + br[i]) * ldb + kk + bc[i]];
            }
        }

        const uint32_t abuf = afrag + buf * ASTG;
        const uint32_t bbuf = bfrag + buf * (MODE == 0 ? BSTG0 : BSTG1);

        if (MODE == 0) {
#pragma unroll
            for (int kc = 0; kc < 2; kc++) {
                uint32_t af[4][4];
#pragma unroll
                for (int mf = 0; mf < 4; mf++)
                    ldsm4(af[mf], abuf + (uint32_t)((wm * 64 + mf * 16) * 80 + kc * 32));
#pragma unroll
                for (int nf = 0; nf < 2; nf++) {
                    uint32_t kb[4];
                    ldsm4t(kb, bbuf + (uint32_t)(kc * 4352 + wn * 64 + nf * 32));
#pragma unroll
                    for (int mf = 0; mf < 4; mf++) {
                        mma_bf16(acc[mf][nf * 2], af[mf], kb[0], kb[1]);
                        mma_bf16(acc[mf][nf * 2 + 1], af[mf], kb[2], kb[3]);
                    }
                }
            }
        } else {
            uint32_t vb[4][4];
#pragma unroll
            for (int j = 0; j < 4; j++)
                ldsm4(vb[j], bbuf + (uint32_t)((wn * 32 + j * 8) * 80));
#pragma unroll
            for (int kc = 0; kc < 2; kc++) {
                uint32_t af[4][4];
#pragma unroll
                for (int mf = 0; mf < 4; mf++)
                    ldsm4(af[mf], abuf + (uint32_t)((wm * 64 + mf * 16) * 80 + kc * 32));
#pragma unroll
                for (int j = 0; j < 4; j++)
#pragma unroll
                    for (int mf = 0; mf < 4; mf++)
                        mma_bf16(acc[mf][j], af[mf], vb[j][2 * kc], vb[j][2 * kc + 1]);
            }
        }

        if (it + 1 < 16) {
            const int nb = buf ^ 1;
#pragma unroll
            for (int i = 0; i < 2; i++) {
                *(uint4*)&As[nb][ar[i]][ac[i]] = pa[i];
                if (MODE == 0) *(uint4*)&Bs[nb][br[i] * 136 + bc[i]] = pb[i];
                else           *(uint4*)&Bs[nb][br[i] * 40 + bc[i]] = pb[i];
            }
        }
        __syncthreads();
    }

    // epilogue
#pragma unroll
    for (int mf = 0; mf < 4; mf++) {
        int m = m0 + wm * 64 + mf * 16 + g;
        float bi0 = bias[m], bi1 = bias[m + 8];
#pragma unroll
        for (int nf = 0; nf < 4; nf++) {
            int n = n0 + wn * 32 + nf * 8 + tg * 2;
            float v0 = acc[mf][nf][0] + bi0, v1 = acc[mf][nf][1] + bi0;
            float v2 = acc[mf][nf][2] + bi1, v3 = acc[mf][nf][3] + bi1;
            if (MODE == 0) {
                *(uint32_t*)&Ch[(size_t)m * ldc + n] = packb(v0, v1);
                *(uint32_t*)&Ch[(size_t)(m + 8) * ldc + n] = packb(v2, v3);
            } else {
                float2 r0 = *(const float2*)&resid[(size_t)m * ldc + n];
                float2 r1 = *(const float2*)&resid[(size_t)(m + 8) * ldc + n];
                *(float2*)&Cf[(size_t)m * ldc + n] = make_float2(v0 + r0.x, v1 + r0.y);
                *(float2*)&Cf[(size_t)(m + 8) * ldc + n] = make_float2(v2 + r1.x, v3 + r1.y);
            }
        }
    }
}

// ---------------- fused flash attention ---------------------------------------
// 4 warps x 32 q-rows = 128-row q tile, 128 threads, KV tile 64, double-buffered
// cp.async. S in log2 units. P via ex2.bf16x2 into A-frags. l via constant
// ones B-fragment (tensor-core row sum).
#define KSTG 9216    // 64*72*2
#define VSTG 9216    // 64*72*2

__global__ void __launch_bounds__(128)
flash_attn(const __nv_bfloat16* __restrict__ qkv, __nv_bfloat16* __restrict__ aoT) {
    __shared__ __nv_bfloat16 Ksm[2][64][72];  // [d][m]
    __shared__ __nv_bfloat16 Vsm[2][64][72];  // [d][m]
    const int tid = threadIdx.x;
    const int w = tid >> 5, lane = tid & 31;
    const int g = lane >> 2, tg = lane & 3;

    const int b = blockIdx.z, h = blockIdx.y;
    const size_t CN = (size_t)CCH * NTOK;
    const __nv_bfloat16* qg = qkv + (size_t)b * 3 * CN + (size_t)(h * HD) * NTOK;
    const __nv_bfloat16* kg = qg + CN;
    const __nv_bfloat16* vg = qg + 2 * CN;

    const int nq0 = blockIdx.x * 128 + w * 32;

    // constant ones B-fragment for l = P @ 1 (ones at output col 0)
    const uint32_t lb1 = (g == 0) ? 0x3F803F80u : 0u;

    // cp.async loader: 4 K + 4 V 16B ops per thread per tile
    int ld_d[4], ld_m[4];
    uint32_t kdst[4], vdst[4];
#pragma unroll
    for (int i = 0; i < 4; i++) {
        int e = tid + i * 128;
        ld_d[i] = e >> 3; ld_m[i] = (e & 7) * 8;
        kdst[i] = (uint32_t)__cvta_generic_to_shared(&Ksm[0][ld_d[i]][ld_m[i]]);
        vdst[i] = (uint32_t)__cvta_generic_to_shared(&Vsm[0][ld_d[i]][ld_m[i]]);
    }
#pragma unroll
    for (int i = 0; i < 4; i++) {
        CP_ASYNC16(kdst[i], kg + (size_t)ld_d[i] * NTOK + ld_m[i]);
        CP_ASYNC16(vdst[i], vg + (size_t)ld_d[i] * NTOK + ld_m[i]);
    }
    CP_COMMIT();

    // Q fragments (scale * log2e folded in)
    const float qs = 0.125f * LOG2E;
    uint32_t qa[2][4][4];
#pragma unroll
    for (int s = 0; s < 2; s++)
#pragma unroll
        for (int kc = 0; kc < 4; kc++) {
            int d0 = kc * 16 + 2 * tg;
#pragma unroll
            for (int rr = 0; rr < 2; rr++) {
                int q = nq0 + s * 16 + g + rr * 8;
                float lo0 = __bfloat162float(qg[(size_t)d0 * NTOK + q]) * qs;
                float hi0 = __bfloat162float(qg[(size_t)(d0 + 1) * NTOK + q]) * qs;
                float lo8 = __bfloat162float(qg[(size_t)(d0 + 8) * NTOK + q]) * qs;
                float hi8 = __bfloat162float(qg[(size_t)(d0 + 9) * NTOK + q]) * qs;
                qa[s][kc][rr] = packb(lo0, hi0);
                qa[s][kc][rr + 2] = packb(lo8, hi8);
            }
        }

    float o[2][8][4];
    float o_l[2][4];
#pragma unroll
    for (int s = 0; s < 2; s++) {
#pragma unroll
        for (int i = 0; i < 8; i++)
#pragma unroll
            for (int j = 0; j < 4; j++) o[s][i][j] = 0.f;
#pragma unroll
        for (int j = 0; j < 4; j++) o_l[s][j] = 0.f;
    }
    float mrow[2][2] = {{-1e30f, -1e30f}, {-1e30f, -1e30f}};

    const uint32_t ksm0 = (uint32_t)__cvta_generic_to_shared(&Ksm[0][0][0]);
    const uint32_t vsm0 = (uint32_t)__cvta_generic_to_shared(&Vsm[0][0][0]);
    const int mat = lane >> 3, r = lane & 7;
    const uint32_t kfrag = ksm0 + (uint32_t)(((mat & 1) * 8 + r) * 144 + (mat >> 1) * 16);
    const uint32_t vfrag = vsm0 + (uint32_t)(r * 144 + mat * 16);

    for (int kt = 0; kt < NTOK / 64; kt++) {
        const int st = kt & 1;
        CP_WAIT_ALL();
        __syncthreads();
        if (kt + 1 < NTOK / 64) {
            int mt = (kt + 1) * 64, s2 = st ^ 1;
#pragma unroll
            for (int i = 0; i < 4; i++) {
                CP_ASYNC16(kdst[i] + s2 * KSTG, kg + (size_t)ld_d[i] * NTOK + mt + ld_m[i]);
                CP_ASYNC16(vdst[i] + s2 * VSTG, vg + (size_t)ld_d[i] * NTOK + mt + ld_m[i]);
            }
            CP_COMMIT();
        }
        const uint32_t kst = kfrag + st * KSTG;
        const uint32_t vst = vfrag + st * VSTG;

        // ---- S = Q^T K (log2 units) ----
        float c[2][8][4];
#pragma unroll
        for (int s = 0; s < 2; s++)
#pragma unroll
            for (int nt = 0; nt < 8; nt++)
                c[s][nt][0] = c[s][nt][1] = c[s][nt][2] = c[s][nt][3] = 0.f;
#pragma unroll
        for (int p = 0; p < 4; p++)
#pragma unroll
            for (int kc = 0; kc < 4; kc++) {
                uint32_t kb[4];
                ldsm4t(kb, kst + (uint32_t)(kc * 2304 + p * 32));
                mma_bf16(c[0][2 * p], qa[0][kc], kb[0], kb[1]);
                mma_bf16(c[1][2 * p], qa[1][kc], kb[0], kb[1]);
                mma_bf16(c[0][2 * p + 1], qa[0][kc], kb[2], kb[3]);
                mma_bf16(c[1][2 * p + 1], qa[1][kc], kb[2], kb[3]);
            }

        // ---- online softmax: max, conditional rescale, packed bf16 exp2 ----
        uint32_t pa[2][4][4];
#pragma unroll
        for (int s = 0; s < 2; s++) {
            float tm0 = -1e30f, tm1 = -1e30f;
#pragma unroll
            for (int nt = 0; nt < 8; nt++) {
                tm0 = fmaxf(tm0, fmaxf(c[s][nt][0], c[s][nt][1]));
                tm1 = fmaxf(tm1, fmaxf(c[s][nt][2], c[s][nt][3]));
            }
            tm0 = fmaxf(tm0, __shfl_xor_sync(0xffffffffu, tm0, 1));
            tm0 = fmaxf(tm0, __shfl_xor_sync(0xffffffffu, tm0, 2));
            tm1 = fmaxf(tm1, __shfl_xor_sync(0xffffffffu, tm1, 1));
            tm1 = fmaxf(tm1, __shfl_xor_sync(0xffffffffu, tm1, 2));
            float nm0 = fmaxf(mrow[s][0], tm0), nm1 = fmaxf(mrow[s][1], tm1);
            if (nm0 != mrow[s][0] || nm1 != mrow[s][1]) {
                float a0 = ex2f(mrow[s][0] - nm0), a1 = ex2f(mrow[s][1] - nm1);
                mrow[s][0] = nm0; mrow[s][1] = nm1;
#pragma unroll
                for (int nt = 0; nt < 8; nt++) {
                    o[s][nt][0] *= a0; o[s][nt][1] *= a0;
                    o[s][nt][2] *= a1; o[s][nt][3] *= a1;
                }
                o_l[s][0] *= a0; o_l[s][1] *= a0;
                o_l[s][2] *= a1; o_l[s][3] *= a1;
            }
            uint32_t pe0[8], pe1[8];
#pragma unroll
            for (int nt = 0; nt < 8; nt++) {
                pe0[nt] = ex2b(c[s][nt][0] - nm0, c[s][nt][1] - nm0);
                pe1[nt] = ex2b(c[s][nt][2] - nm1, c[s][nt][3] - nm1);
            }
#pragma unroll
            for (int mc = 0; mc < 4; mc++) {
                pa[s][mc][0] = pe0[2 * mc];
                pa[s][mc][1] = pe1[2 * mc];
                pa[s][mc][2] = pe0[2 * mc + 1];
                pa[s][mc][3] = pe1[2 * mc + 1];
            }
        }

        // ---- l += P @ ones (constant B fragment) ----
#pragma unroll
        for (int mc = 0; mc < 4; mc++) {
            mma_bf16(o_l[0], pa[0][mc], lb1, lb1);
            mma_bf16(o_l[1], pa[1][mc], lb1, lb1);
        }

        // ---- O += P @ V^T ----
#pragma unroll
        for (int dt = 0; dt < 8; dt++)
#pragma unroll
            for (int mcp = 0; mcp < 2; mcp++) {
                uint32_t vb[4];
                ldsm4(vb, vst + (uint32_t)(dt * 1152 + mcp * 64));
                mma_bf16(o[0][dt], pa[0][2 * mcp], vb[0], vb[1]);
                mma_bf16(o[1][dt], pa[1][2 * mcp], vb[0], vb[1]);
                mma_bf16(o[0][dt], pa[0][2 * mcp + 1], vb[2], vb[3]);
                mma_bf16(o[1][dt], pa[1][2 * mcp + 1], vb[2], vb[3]);
            }
    }

    // ---- epilogue ----
    __nv_bfloat16* outp = aoT + (size_t)b * CN + (size_t)(h * HD);
#pragma unroll
    for (int s = 0; s < 2; s++) {
        float l0 = __shfl_sync(0xffffffffu, o_l[s][0], lane & 28);
        float l1 = __shfl_sync(0xffffffffu, o_l[s][2], lane & 28);
        float inv0 = 1.f / l0, inv1 = 1.f / l1;
        int q0 = nq0 + s * 16;
#pragma unroll
        for (int dt = 0; dt < 8; dt++) {
            *(uint32_t*)&outp[(size_t)(q0 + g) * CCH + dt * 8 + tg * 2] =
                packb(o[s][dt][0] * inv0, o[s][dt][1] * inv0);
            *(uint32_t*)&outp[(size_t)(q0 + g + 8) * CCH + dt * 8 + tg * 2] =
                packb(o[s][dt][2] * inv1, o[s][dt][3] * inv1);
        }
    }
}

// ---------------- launch ------------------------------------------------------
extern "C" void kernel_launch(void* const* d_in, const int* in_sizes, int n_in,
                              void* d_out, int out_size) {
    const float* x      = (const float*)d_in[0];
    const float* norm_w = (const float*)d_in[1];
    const float* norm_b = (const float*)d_in[2];
    const float* qkv_w  = (const float*)d_in[3];
    const float* qkv_b  = (const float*)d_in[4];
    const float* proj_w = (const float*)d_in[5];
    const float* proj_b = (const float*)d_in[6];
    float* out = (float*)d_out;

    __nv_bfloat16 *hn, *qkv, *aoT, *qkvwb, *projwb;
    cudaGetSymbolAddress((void**)&hn,     g_hn);
    cudaGetSymbolAddress((void**)&qkv,    g_qkv);
    cudaGetSymbolAddress((void**)&aoT,    g_aoT);
    cudaGetSymbolAddress((void**)&qkvwb,  g_qkvwb);
    cudaGetSymbolAddress((void**)&projwb, g_projwb);

    const size_t CN = (size_t)CCH * NTOK;

    // 0) weight fp32 -> bf16
    cvt_w<<<(3 * CCH * CCH + CCH * CCH) / 4 / 256, 256>>>(qkv_w, proj_w);

    // 1) GroupNorm (writes bf16 hn)
    gn_stats<<<dim3(8, BATCH * GROUPS), 256>>>(x);
    gn_apply<<<dim3(8, BATCH * GROUPS), 256>>>(x, norm_w, norm_b);

    // 2) QKV GEMM: bf16 W [1536,512] x hn [512,4096] -> bf16 qkv
    gemm2<0><<<dim3(NTOK / 128, (3 * CCH) / 128, BATCH), 256>>>(
        qkvwb, hn, qkv, CCH, NTOK, NTOK,
        CN, 3 * CN, qkv_b, nullptr, 0);

    // 3) fused attention
    flash_attn<<<dim3(NTOK / 128, NH, BATCH), 128>>>(qkv, aoT);

    // 4) proj + bias + residual -> fp32 out
    gemm2<1><<<dim3(NTOK / 128, CCH / 128, BATCH), 256>>>(
        projwb, aoT, out, CCH, CCH, NTOK,
        CN, CN, proj_b, x, CN);
}

// round 9
// speedup vs baseline: 15.6120x; 1.0549x over previous
#include <cuda_runtime.h>
#include <cuda_bf16.h>
#include <math.h>
#include <stdint.h>

#define BATCH 2
#define CCH 512
#define NH 8
#define HD 64
#define GROUPS 32
#define NTOK 4096
#define EPS 1e-5f
#define LOG2E 1.44269504f

// ---------------- scratch (static device globals; no allocation) -------------
__device__ __nv_bfloat16 g_hn[(size_t)BATCH * CCH * NTOK];          // 8 MB
__device__ __nv_bfloat16 g_qkv[(size_t)BATCH * 3 * CCH * NTOK];     // 25 MB
__device__ __nv_bfloat16 g_aoT[(size_t)BATCH * NTOK * CCH];         // 8 MB [b][n][c]
__device__ __nv_bfloat16 g_qkvwb[3 * CCH * CCH];                    // 1.5 MB
__device__ __nv_bfloat16 g_projwb[CCH * CCH];                       // 0.5 MB
__device__ float g_gnpart[BATCH * GROUPS][8][2];

// ---------------- helpers -----------------------------------------------------
__device__ __forceinline__ uint32_t packb(float lo, float hi) {
    __nv_bfloat162 t = __floats2bfloat162_rn(lo, hi);
    return *(uint32_t*)&t;
}
__device__ __forceinline__ float ex2f(float x) {
    float y;
    asm("ex2.approx.f32 %0, %1;" : "=f"(y) : "f"(x));
    return y;
}
__device__ __forceinline__ uint32_t ex2b(float lo, float hi) {
    __nv_bfloat162 t = __floats2bfloat162_rn(lo, hi);
    uint32_t u = *(uint32_t*)&t, y;
    asm("ex2.approx.ftz.bf16x2 %0, %1;" : "=r"(y) : "r"(u));
    return y;
}
__device__ __forceinline__ void mma_bf16(float c[4], const uint32_t a[4],
                                         uint32_t b0, uint32_t b1) {
    asm volatile(
        "mma.sync.aligned.m16n8k16.row.col.f32.bf16.bf16.f32 "
        "{%0,%1,%2,%3}, {%4,%5,%6,%7}, {%8,%9}, {%0,%1,%2,%3};\n"
        : "+f"(c[0]), "+f"(c[1]), "+f"(c[2]), "+f"(c[3])
        : "r"(a[0]), "r"(a[1]), "r"(a[2]), "r"(a[3]), "r"(b0), "r"(b1));
}
__device__ __forceinline__ void ldsm4t(uint32_t r[4], uint32_t addr) {
    asm volatile(
        "ldmatrix.sync.aligned.m8n8.x4.trans.shared.b16 {%0,%1,%2,%3}, [%4];"
        : "=r"(r[0]), "=r"(r[1]), "=r"(r[2]), "=r"(r[3]) : "r"(addr));
}
__device__ __forceinline__ void ldsm4(uint32_t r[4], uint32_t addr) {
    asm volatile(
        "ldmatrix.sync.aligned.m8n8.x4.shared.b16 {%0,%1,%2,%3}, [%4];"
        : "=r"(r[0]), "=r"(r[1]), "=r"(r[2]), "=r"(r[3]) : "r"(addr));
}
#define CP_ASYNC16(dst, src) \
    asm volatile("cp.async.cg.shared.global [%0], [%1], 16;" :: "r"(dst), "l"(src))
#define CP_COMMIT() asm volatile("cp.async.commit_group;")
#define CP_WAIT0() asm volatile("cp.async.wait_group 0;")
#define CP_WAIT1() asm volatile("cp.async.wait_group 1;")

// ---------------- weight conversion fp32 -> bf16 ------------------------------
__global__ void cvt_w(const float* __restrict__ qkv_w, const float* __restrict__ proj_w) {
    const int NQ = 3 * CCH * CCH / 4;
    int i = blockIdx.x * 256 + threadIdx.x;
    if (i < NQ) {
        float4 v = ((const float4*)qkv_w)[i];
        uint2 o; o.x = packb(v.x, v.y); o.y = packb(v.z, v.w);
        ((uint2*)g_qkvwb)[i] = o;
    } else {
        int j = i - NQ;
        float4 v = ((const float4*)proj_w)[j];
        uint2 o; o.x = packb(v.x, v.y); o.y = packb(v.z, v.w);
        ((uint2*)g_projwb)[j] = o;
    }
}

// ---------------- GroupNorm: stats + apply ------------------------------------
__global__ void gn_stats(const float* __restrict__ x) {
    int bg = blockIdx.y, sl = blockIdx.x, tid = threadIdx.x;
    const float4* xp = (const float4*)x + (size_t)bg * 16384 + sl * 2048;
    float s = 0.f, s2 = 0.f;
    for (int i = tid; i < 2048; i += 256) {
        float4 v = xp[i];
        s += v.x + v.y + v.z + v.w;
        s2 += v.x * v.x + v.y * v.y + v.z * v.z + v.w * v.w;
    }
    __shared__ float sh[256], sh2[256];
    sh[tid] = s; sh2[tid] = s2;
    __syncthreads();
    for (int o = 128; o > 0; o >>= 1) {
        if (tid < o) { sh[tid] += sh[tid + o]; sh2[tid] += sh2[tid + o]; }
        __syncthreads();
    }
    if (tid == 0) {
        g_gnpart[bg][sl][0] = sh[0];
        g_gnpart[bg][sl][1] = sh2[0];
    }
}

__global__ void gn_apply(const float* __restrict__ x,
                         const float* __restrict__ w,
                         const float* __restrict__ b) {
    int bg = blockIdx.y, sl = blockIdx.x, tid = threadIdx.x;
    float S = 0.f, S2 = 0.f;
#pragma unroll
    for (int i = 0; i < 8; i++) {
        S += g_gnpart[bg][i][0];
        S2 += g_gnpart[bg][i][1];
    }
    float mean = S / 65536.f;
    float var  = S2 / 65536.f - mean * mean;
    float inv  = rsqrtf(var + EPS);
    int g = bg % GROUPS;
    const float4* xp = (const float4*)x + (size_t)bg * 16384 + sl * 2048;
    uint2* hp = (uint2*)(g_hn + (size_t)bg * 65536 + sl * 8192);
    for (int i = tid; i < 2048; i += 256) {
        int ch = g * 16 + sl * 2 + (i >> 10);
        float sc = inv * w[ch];
        float off = b[ch] - mean * sc;
        float4 v = xp[i];
        uint2 o;
        o.x = packb(v.x * sc + off, v.y * sc + off);
        o.y = packb(v.z * sc + off, v.w * sc + off);
        hp[i] = o;
    }
}

// ---------------- bf16 GEMM v3: cp.async, 3-stage, 1 sync/iter ----------------
// C[m,n] = sum_k A[m,k]*B[..] + bias[m] (+resid)
// A bf16 [m][k] row-major (weights). K=512 (16 iters of 32).
// MODE 0 (QKV): B bf16 [k][n], C bf16.  MODE 1 (PROJ): B bf16 [n][k], C fp32+resid.
#define ASTG 10240   // 128*40*2
#define BSTG0 8704   // 32*136*2
#define BSTG1 10240  // 128*40*2
template <int MODE>
__global__ void __launch_bounds__(256, 2)
gemm3(const __nv_bfloat16* __restrict__ A, const __nv_bfloat16* __restrict__ B,
      void* __restrict__ Cv, int lda, int ldb, int ldc,
      size_t sB, size_t sC,
      const float* __restrict__ bias,
      const float* __restrict__ resid, size_t sR) {
    constexpr int BSTG = (MODE == 0) ? BSTG0 : BSTG1;
    extern __shared__ __align__(16) char gsm[];
    const uint32_t asmb = (uint32_t)__cvta_generic_to_shared(gsm);
    const uint32_t bsmb = asmb + 3 * ASTG;

    const int tid = threadIdx.x;
    const int w = tid >> 5, lane = tid & 31;
    const int g = lane >> 2, tg = lane & 3;
    const int wm = w >> 2, wn = w & 3;
    const int m0 = blockIdx.y * 128;
    const int n0 = blockIdx.x * 128;

    B += (size_t)blockIdx.z * sB;
    float* Cf = (float*)Cv + (MODE == 1 ? (size_t)blockIdx.z * sC : 0);
    __nv_bfloat16* Ch = (__nv_bfloat16*)Cv + (MODE == 0 ? (size_t)blockIdx.z * sC : 0);
    if (MODE == 1 && resid) resid += (size_t)blockIdx.z * sR;

    // loader indices (2 x 16B for A and B each)
    int ar[2], ac[2], br[2], bc[2];
    uint32_t adst[2], bdst[2];
#pragma unroll
    for (int i = 0; i < 2; i++) {
        int e = tid + i * 256;
        ar[i] = e >> 2; ac[i] = (e & 3) * 8;
        adst[i] = asmb + (uint32_t)((ar[i] * 40 + ac[i]) * 2);
        if (MODE == 0) {
            br[i] = e >> 4; bc[i] = (e & 15) * 8;
            bdst[i] = bsmb + (uint32_t)((br[i] * 136 + bc[i]) * 2);
        } else {
            br[i] = e >> 2; bc[i] = (e & 3) * 8;
            bdst[i] = bsmb + (uint32_t)((br[i] * 40 + bc[i]) * 2);
        }
    }

#define G3_ISSUE(kk, st)                                                        \
    do {                                                                        \
        _Pragma("unroll")                                                       \
        for (int i = 0; i < 2; i++) {                                           \
            CP_ASYNC16(adst[i] + (st) * ASTG,                                   \
                       &A[(size_t)(m0 + ar[i]) * lda + (kk) + ac[i]]);          \
            if (MODE == 0)                                                      \
                CP_ASYNC16(bdst[i] + (st) * BSTG,                               \
                           &B[(size_t)((kk) + br[i]) * ldb + n0 + bc[i]]);      \
            else                                                                \
                CP_ASYNC16(bdst[i] + (st) * BSTG,                               \
                           &B[(size_t)(n0 + br[i]) * ldb + (kk) + bc[i]]);      \
        }                                                                       \
        CP_COMMIT();                                                            \
    } while (0)

    G3_ISSUE(0, 0);
    G3_ISSUE(32, 1);

    // fragment base addresses
    const uint32_t afrag = asmb + (uint32_t)((lane & 15) * 80 + (lane >> 4) * 16);
    uint32_t bfrag;
    if (MODE == 0)
        bfrag = bsmb + (uint32_t)((((lane >> 3 & 1) * 8) + (lane & 7)) * 272 + (lane >> 4) * 16);
    else
        bfrag = bsmb + (uint32_t)((lane & 7) * 80 + (lane >> 3) * 16);

    float acc[4][4][4];
#pragma unroll
    for (int mf = 0; mf < 4; mf++)
#pragma unroll
        for (int nf = 0; nf < 4; nf++)
#pragma unroll
            for (int r = 0; r < 4; r++) acc[mf][nf][r] = 0.f;

    for (int it = 0; it < 16; it++) {
        const int st = it % 3;
        if (it + 1 < 16) CP_WAIT1(); else CP_WAIT0();
        __syncthreads();
        if (it + 2 < 16) G3_ISSUE((it + 2) * 32, (it + 2) % 3);

        const uint32_t abuf = afrag + st * ASTG;
        const uint32_t bbuf = bfrag + st * BSTG;

        if (MODE == 0) {
#pragma unroll
            for (int kc = 0; kc < 2; kc++) {
                uint32_t af[4][4];
#pragma unroll
                for (int mf = 0; mf < 4; mf++)
                    ldsm4(af[mf], abuf + (uint32_t)((wm * 64 + mf * 16) * 80 + kc * 32));
#pragma unroll
                for (int nf = 0; nf < 2; nf++) {
                    uint32_t kb[4];
                    ldsm4t(kb, bbuf + (uint32_t)(kc * 4352 + wn * 64 + nf * 32));
#pragma unroll
                    for (int mf = 0; mf < 4; mf++) {
                        mma_bf16(acc[mf][nf * 2], af[mf], kb[0], kb[1]);
                        mma_bf16(acc[mf][nf * 2 + 1], af[mf], kb[2], kb[3]);
                    }
                }
            }
        } else {
            uint32_t vb[4][4];
#pragma unroll
            for (int j = 0; j < 4; j++)
                ldsm4(vb[j], bbuf + (uint32_t)((wn * 32 + j * 8) * 80));
#pragma unroll
            for (int kc = 0; kc < 2; kc++) {
                uint32_t af[4][4];
#pragma unroll
                for (int mf = 0; mf < 4; mf++)
                    ldsm4(af[mf], abuf + (uint32_t)((wm * 64 + mf * 16) * 80 + kc * 32));
#pragma unroll
                for (int j = 0; j < 4; j++)
#pragma unroll
                    for (int mf = 0; mf < 4; mf++)
                        mma_bf16(acc[mf][j], af[mf], vb[j][2 * kc], vb[j][2 * kc + 1]);
            }
        }
    }

    // epilogue
#pragma unroll
    for (int mf = 0; mf < 4; mf++) {
        int m = m0 + wm * 64 + mf * 16 + g;
        float bi0 = bias[m], bi1 = bias[m + 8];
#pragma unroll
        for (int nf = 0; nf < 4; nf++) {
            int n = n0 + wn * 32 + nf * 8 + tg * 2;
            float v0 = acc[mf][nf][0] + bi0, v1 = acc[mf][nf][1] + bi0;
            float v2 = acc[mf][nf][2] + bi1, v3 = acc[mf][nf][3] + bi1;
            if (MODE == 0) {
                *(uint32_t*)&Ch[(size_t)m * ldc + n] = packb(v0, v1);
                *(uint32_t*)&Ch[(size_t)(m + 8) * ldc + n] = packb(v2, v3);
            } else {
                float2 r0 = *(const float2*)&resid[(size_t)m * ldc + n];
                float2 r1 = *(const float2*)&resid[(size_t)(m + 8) * ldc + n];
                *(float2*)&Cf[(size_t)m * ldc + n] = make_float2(v0 + r0.x, v1 + r0.y);
                *(float2*)&Cf[(size_t)(m + 8) * ldc + n] = make_float2(v2 + r1.x, v3 + r1.y);
            }
        }
    }
}

// ---------------- fused flash attention ---------------------------------------
// 4 warps x 32 q-rows, 128 threads, KV tile 64, 3-stage cp.async, 1 sync/tile.
#define KSTG 9216    // 64*72*2 per stage (same for V)
#define NKV (NTOK / 64)

__global__ void __launch_bounds__(128)
flash_attn(const __nv_bfloat16* __restrict__ qkv, __nv_bfloat16* __restrict__ aoT) {
    extern __shared__ __align__(16) char fsm[];
    const uint32_t ksmb = (uint32_t)__cvta_generic_to_shared(fsm);
    const uint32_t vsmb = ksmb + 3 * KSTG;

    const int tid = threadIdx.x;
    const int w = tid >> 5, lane = tid & 31;
    const int g = lane >> 2, tg = lane & 3;

    const int b = blockIdx.z, h = blockIdx.y;
    const size_t CN = (size_t)CCH * NTOK;
    const __nv_bfloat16* qg = qkv + (size_t)b * 3 * CN + (size_t)(h * HD) * NTOK;
    const __nv_bfloat16* kg = qg + CN;
    const __nv_bfloat16* vg = qg + 2 * CN;

    const int nq0 = blockIdx.x * 128 + w * 32;

    const uint32_t lb1 = (g == 0) ? 0x3F803F80u : 0u;  // ones B-frag for l

    // cp.async loader: 4 K + 4 V 16B ops per thread per tile
    int ld_d[4], ld_m[4];
    uint32_t kdst[4], vdst[4];
#pragma unroll
    for (int i = 0; i < 4; i++) {
        int e = tid + i * 128;
        ld_d[i] = e >> 3; ld_m[i] = (e & 7) * 8;
        kdst[i] = ksmb + (uint32_t)((ld_d[i] * 72 + ld_m[i]) * 2);
        vdst[i] = vsmb + (uint32_t)((ld_d[i] * 72 + ld_m[i]) * 2);
    }
#define FA_ISSUE(mt, st)                                                       \
    do {                                                                       \
        _Pragma("unroll")                                                      \
        for (int i = 0; i < 4; i++) {                                          \
            CP_ASYNC16(kdst[i] + (st) * KSTG,                                  \
                       kg + (size_t)ld_d[i] * NTOK + (mt) + ld_m[i]);          \
            CP_ASYNC16(vdst[i] + (st) * KSTG,                                  \
                       vg + (size_t)ld_d[i] * NTOK + (mt) + ld_m[i]);          \
        }                                                                      \
        CP_COMMIT();                                                           \
    } while (0)

    FA_ISSUE(0, 0);
    FA_ISSUE(64, 1);

    // Q fragments (scale * log2e folded in)
    const float qs = 0.125f * LOG2E;
    uint32_t qa[2][4][4];
#pragma unroll
    for (int s = 0; s < 2; s++)
#pragma unroll
        for (int kc = 0; kc < 4; kc++) {
            int d0 = kc * 16 + 2 * tg;
#pragma unroll
            for (int rr = 0; rr < 2; rr++) {
                int q = nq0 + s * 16 + g + rr * 8;
                float lo0 = __bfloat162float(qg[(size_t)d0 * NTOK + q]) * qs;
                float hi0 = __bfloat162float(qg[(size_t)(d0 + 1) * NTOK + q]) * qs;
                float lo8 = __bfloat162float(qg[(size_t)(d0 + 8) * NTOK + q]) * qs;
                float hi8 = __bfloat162float(qg[(size_t)(d0 + 9) * NTOK + q]) * qs;
                qa[s][kc][rr] = packb(lo0, hi0);
                qa[s][kc][rr + 2] = packb(lo8, hi8);
            }
        }

    float o[2][8][4];
    float o_l[2][4];
#pragma unroll
    for (int s = 0; s < 2; s++) {
#pragma unroll
        for (int i = 0; i < 8; i++)
#pragma unroll
            for (int j = 0; j < 4; j++) o[s][i][j] = 0.f;
#pragma unroll
        for (int j = 0; j < 4; j++) o_l[s][j] = 0.f;
    }
    float mrow[2][2] = {{-1e30f, -1e30f}, {-1e30f, -1e30f}};

    const int mat = lane >> 3, r = lane & 7;
    const uint32_t kfrag = ksmb + (uint32_t)(((mat & 1) * 8 + r) * 144 + (mat >> 1) * 16);
    const uint32_t vfrag = vsmb + (uint32_t)(r * 144 + mat * 16);

    for (int kt = 0; kt < NKV; kt++) {
        const int st = kt % 3;
        if (kt + 1 < NKV) CP_WAIT1(); else CP_WAIT0();
        __syncthreads();
        if (kt + 2 < NKV) FA_ISSUE((kt + 2) * 64, (kt + 2) % 3);

        const uint32_t kst = kfrag + st * KSTG;
        const uint32_t vst = vfrag + st * KSTG;

        // ---- S = Q^T K (log2 units) ----
        float c[2][8][4];
#pragma unroll
        for (int s = 0; s < 2; s++)
#pragma unroll
            for (int nt = 0; nt < 8; nt++)
                c[s][nt][0] = c[s][nt][1] = c[s][nt][2] = c[s][nt][3] = 0.f;
#pragma unroll
        for (int p = 0; p < 4; p++)
#pragma unroll
            for (int kc = 0; kc < 4; kc++) {
                uint32_t kb[4];
                ldsm4t(kb, kst + (uint32_t)(kc * 2304 + p * 32));
                mma_bf16(c[0][2 * p], qa[0][kc], kb[0], kb[1]);
                mma_bf16(c[1][2 * p], qa[1][kc], kb[0], kb[1]);
                mma_bf16(c[0][2 * p + 1], qa[0][kc], kb[2], kb[3]);
                mma_bf16(c[1][2 * p + 1], qa[1][kc], kb[2], kb[3]);
            }

        // ---- online softmax ----
        uint32_t pa[2][4][4];
#pragma unroll
        for (int s = 0; s < 2; s++) {
            float tm0 = -1e30f, tm1 = -1e30f;
#pragma unroll
            for (int nt = 0; nt < 8; nt++) {
                tm0 = fmaxf(tm0, fmaxf(c[s][nt][0], c[s][nt][1]));
                tm1 = fmaxf(tm1, fmaxf(c[s][nt][2], c[s][nt][3]));
            }
            tm0 = fmaxf(tm0, __shfl_xor_sync(0xffffffffu, tm0, 1));
            tm0 = fmaxf(tm0, __shfl_xor_sync(0xffffffffu, tm0, 2));
            tm1 = fmaxf(tm1, __shfl_xor_sync(0xffffffffu, tm1, 1));
            tm1 = fmaxf(tm1, __shfl_xor_sync(0xffffffffu, tm1, 2));
            float nm0 = fmaxf(mrow[s][0], tm0), nm1 = fmaxf(mrow[s][1], tm1);
            if (nm0 != mrow[s][0] || nm1 != mrow[s][1]) {
                float a0 = ex2f(mrow[s][0] - nm0), a1 = ex2f(mrow[s][1] - nm1);
                mrow[s][0] = nm0; mrow[s][1] = nm1;
#pragma unroll
                for (int nt = 0; nt < 8; nt++) {
                    o[s][nt][0] *= a0; o[s][nt][1] *= a0;
                    o[s][nt][2] *= a1; o[s][nt][3] *= a1;
                }
                o_l[s][0] *= a0; o_l[s][1] *= a0;
                o_l[s][2] *= a1; o_l[s][3] *= a1;
            }
            uint32_t pe0[8], pe1[8];
#pragma unroll
            for (int nt = 0; nt < 8; nt++) {
                pe0[nt] = ex2b(c[s][nt][0] - nm0, c[s][nt][1] - nm0);
                pe1[nt] = ex2b(c[s][nt][2] - nm1, c[s][nt][3] - nm1);
            }
#pragma unroll
            for (int mc = 0; mc < 4; mc++) {
                pa[s][mc][0] = pe0[2 * mc];
                pa[s][mc][1] = pe1[2 * mc];
                pa[s][mc][2] = pe0[2 * mc + 1];
                pa[s][mc][3] = pe1[2 * mc + 1];
            }
        }

        // ---- l += P @ ones ----
#pragma unroll
        for (int mc = 0; mc < 4; mc++) {
            mma_bf16(o_l[0], pa[0][mc], lb1, lb1);
            mma_bf16(o_l[1], pa[1][mc], lb1, lb1);
        }

        // ---- O += P @ V^T ----
#pragma unroll
        for (int dt = 0; dt < 8; dt++)
#pragma unroll
            for (int mcp = 0; mcp < 2; mcp++) {
                uint32_t vb[4];
                ldsm4(vb, vst + (uint32_t)(dt * 1152 + mcp * 64));
                mma_bf16(o[0][dt], pa[0][2 * mcp], vb[0], vb[1]);
                mma_bf16(o[1][dt], pa[1][2 * mcp], vb[0], vb[1]);
                mma_bf16(o[0][dt], pa[0][2 * mcp + 1], vb[2], vb[3]);
                mma_bf16(o[1][dt], pa[1][2 * mcp + 1], vb[2], vb[3]);
            }
    }

    // ---- epilogue ----
    __nv_bfloat16* outp = aoT + (size_t)b * CN + (size_t)(h * HD);
#pragma unroll
    for (int s = 0; s < 2; s++) {
        float l0 = __shfl_sync(0xffffffffu, o_l[s][0], lane & 28);
        float l1 = __shfl_sync(0xffffffffu, o_l[s][2], lane & 28);
        float inv0 = 1.f / l0, inv1 = 1.f / l1;
        int q0 = nq0 + s * 16;
#pragma unroll
        for (int dt = 0; dt < 8; dt++) {
            *(uint32_t*)&outp[(size_t)(q0 + g) * CCH + dt * 8 + tg * 2] =
                packb(o[s][dt][0] * inv0, o[s][dt][1] * inv0);
            *(uint32_t*)&outp[(size_t)(q0 + g + 8) * CCH + dt * 8 + tg * 2] =
                packb(o[s][dt][2] * inv1, o[s][dt][3] * inv1);
        }
    }
}

// ---------------- launch ------------------------------------------------------
extern "C" void kernel_launch(void* const* d_in, const int* in_sizes, int n_in,
                              void* d_out, int out_size) {
    const float* x      = (const float*)d_in[0];
    const float* norm_w = (const float*)d_in[1];
    const float* norm_b = (const float*)d_in[2];
    const float* qkv_w  = (const float*)d_in[3];
    const float* qkv_b  = (const float*)d_in[4];
    const float* proj_w = (const float*)d_in[5];
    const float* proj_b = (const float*)d_in[6];
    float* out = (float*)d_out;

    __nv_bfloat16 *hn, *qkv, *aoT, *qkvwb, *projwb;
    cudaGetSymbolAddress((void**)&hn,     g_hn);
    cudaGetSymbolAddress((void**)&qkv,    g_qkv);
    cudaGetSymbolAddress((void**)&aoT,    g_aoT);
    cudaGetSymbolAddress((void**)&qkvwb,  g_qkvwb);
    cudaGetSymbolAddress((void**)&projwb, g_projwb);

    const size_t CN = (size_t)CCH * NTOK;

    const int SM_G0 = 3 * (ASTG + BSTG0);  // 56832
    const int SM_G1 = 3 * (ASTG + BSTG1);  // 61440
    const int SM_FA = 6 * KSTG;            // 55296
    static int attr_done = 0;
    if (!attr_done) {
        cudaFuncSetAttribute(gemm3<0>, cudaFuncAttributeMaxDynamicSharedMemorySize, SM_G0);
        cudaFuncSetAttribute(gemm3<1>, cudaFuncAttributeMaxDynamicSharedMemorySize, SM_G1);
        cudaFuncSetAttribute(flash_attn, cudaFuncAttributeMaxDynamicSharedMemorySize, SM_FA);
        attr_done = 1;
    }

    // 0) weight fp32 -> bf16
    cvt_w<<<(3 * CCH * CCH + CCH * CCH) / 4 / 256, 256>>>(qkv_w, proj_w);

    // 1) GroupNorm (writes bf16 hn)
    gn_stats<<<dim3(8, BATCH * GROUPS), 256>>>(x);
    gn_apply<<<dim3(8, BATCH * GROUPS), 256>>>(x, norm_w, norm_b);

    // 2) QKV GEMM: bf16 W [1536,512] x hn [512,4096] -> bf16 qkv
    gemm3<0><<<dim3(NTOK / 128, (3 * CCH) / 128, BATCH), 256, SM_G0>>>(
        qkvwb, hn, qkv, CCH, NTOK, NTOK,
        CN, 3 * CN, qkv_b, nullptr, 0);

    // 3) fused attention
    flash_attn<<<dim3(NTOK / 128, NH, BATCH), 128, SM_FA>>>(qkv, aoT);

    // 4) proj + bias + residual -> fp32 out
    gemm3<1><<<dim3(NTOK / 128, CCH / 128, BATCH), 256, SM_G1>>>(
        projwb, aoT, out, CCH, CCH, NTOK,
        CN, CN, proj_b, x, CN);
}